// round 5
// baseline (speedup 1.0000x reference)
#include <cuda_runtime.h>
#include <cuda_bf16.h>
#include <math.h>
#include <stdint.h>

#define BATCH 16384
#define DIM   512
#define HID   2048

#define BM 256
#define BN 128
#define BK 32
#define THREADS 256

// smem rows padded to 80B (32 bf16 + 16B pad)
#define ROWB   80
#define OA_H   0
#define OA_L   20480
#define OB_H   40960
#define OB_L   51200
#define STAGE  61440
#define NSTAGE 3
#define SMEM_TOTAL (NSTAGE * STAGE)   // 184320

// ---------------- scratch (allocation-free) ----------------
__device__ __nv_bfloat16 g_zh[(size_t)BATCH * DIM],  g_zl[(size_t)BATCH * DIM];
__device__ __nv_bfloat16 g_h1h[(size_t)BATCH * HID], g_h1l[(size_t)BATCH * HID];
__device__ __nv_bfloat16 g_h2h[(size_t)BATCH * HID], g_h2l[(size_t)BATCH * HID];
__device__ __nv_bfloat16 g_d2h[(size_t)BATCH * HID], g_d2l[(size_t)BATCH * HID];
__device__ __nv_bfloat16 g_d1h[(size_t)BATCH * HID], g_d1l[(size_t)BATCH * HID];
__device__ float g_g[(size_t)BATCH * DIM];
__device__ float g_v3[HID];
__device__ __nv_bfloat16 g_W1h[HID * DIM],  g_W1l[HID * DIM];
__device__ __nv_bfloat16 g_W2h[HID * HID],  g_W2l[HID * HID];
__device__ __nv_bfloat16 g_W3h[DIM * HID],  g_W3l[DIM * HID];
__device__ __nv_bfloat16 g_W2Th[HID * HID], g_W2Tl[HID * HID];
__device__ __nv_bfloat16 g_W1Th[DIM * HID], g_W1Tl[DIM * HID];

enum { EPI_H1 = 0, EPI_H2D2 = 1, EPI_OUT = 2, EPI_D1 = 3, EPI_G = 4 };

// ---------------- helpers ----------------
__device__ __forceinline__ uint32_t s2u(const void* p) {
    uint32_t a;
    asm("{ .reg .u64 t; cvta.to.shared.u64 t, %1; cvt.u32.u64 %0, t; }" : "=r"(a) : "l"(p));
    return a;
}

__device__ __forceinline__ void ldsm4(uint32_t* r, uint32_t addr) {
    asm volatile("ldmatrix.sync.aligned.m8n8.x4.shared.b16 {%0,%1,%2,%3}, [%4];"
                 : "=r"(r[0]), "=r"(r[1]), "=r"(r[2]), "=r"(r[3]) : "r"(addr));
}

__device__ __forceinline__ void mma16816(float* c, const uint32_t* a, const uint32_t* b) {
    asm volatile("mma.sync.aligned.m16n8k16.row.col.f32.bf16.bf16.f32 "
                 "{%0,%1,%2,%3}, {%4,%5,%6,%7}, {%8,%9}, {%0,%1,%2,%3};"
                 : "+f"(c[0]), "+f"(c[1]), "+f"(c[2]), "+f"(c[3])
                 : "r"(a[0]), "r"(a[1]), "r"(a[2]), "r"(a[3]), "r"(b[0]), "r"(b[1]));
}

__device__ __forceinline__ void cp16(uint32_t dst, const void* src) {
    asm volatile("cp.async.cg.shared.global [%0], [%1], 16;" :: "r"(dst), "l"(src) : "memory");
}

__device__ __forceinline__ float ftanh(float x) {
    float e = __expf(2.f * x);
    return 1.f - __fdividef(2.f, e + 1.f);
}

__device__ __forceinline__ void split_store(__nv_bfloat16* __restrict__ H,
                                            __nv_bfloat16* __restrict__ L,
                                            size_t off, float x, float y) {
    __nv_bfloat162 h = __floats2bfloat162_rn(x, y);
    __nv_bfloat162 l = __floats2bfloat162_rn(x - __bfloat162float(h.x),
                                             y - __bfloat162float(h.y));
    *reinterpret_cast<__nv_bfloat162*>(H + off) = h;
    *reinterpret_cast<__nv_bfloat162*>(L + off) = l;
}

// tile loader: NR rows x 32 cols bf16 hi+lo via cp.async
template <int NR>
__device__ __forceinline__ void cpTile(uint32_t dstH, uint32_t dstL,
                                       const __nv_bfloat16* __restrict__ srcH,
                                       const __nv_bfloat16* __restrict__ srcL,
                                       int ld, int r0, int k0, int tid) {
#pragma unroll
    for (int i = 0; i < NR / 64; ++i) {
        int idx = tid + i * 256;
        int row = idx >> 2, seg = idx & 3;
        size_t go = (size_t)(r0 + row) * ld + k0 + seg * 8;
        uint32_t so = row * ROWB + seg * 16;
        cp16(dstH + so, srcH + go);
        cp16(dstL + so, srcL + go);
    }
}

// ---------------- split-bf16 warp-MMA GEMM ----------------
// acc[M,N] = (Ah+Al)[M,K] * ((Bh+Bl)[N,K])^T  (3 terms), epilogue per EPI
template <int EPI>
__global__ void __launch_bounds__(THREADS, 1) mma_gemm(
    const __nv_bfloat16* __restrict__ Ah, const __nv_bfloat16* __restrict__ Al,
    const __nv_bfloat16* __restrict__ Bh, const __nv_bfloat16* __restrict__ Bl,
    const float* __restrict__ bias, const float* __restrict__ v3p,
    float* __restrict__ C, int ldc,
    __nv_bfloat16* __restrict__ P1h, __nv_bfloat16* __restrict__ P1l,
    __nv_bfloat16* __restrict__ P2h, __nv_bfloat16* __restrict__ P2l,
    const __nv_bfloat16* __restrict__ Xh, const __nv_bfloat16* __restrict__ Xl,
    int K, int ldp)
{
    extern __shared__ char smem[];
    const uint32_t sb = s2u(smem);
    const int tid = threadIdx.x, lane = tid & 31, wid = tid >> 5;
    const int wm = wid >> 1, wn = wid & 1;          // 4x2 warps, 64x64 each
    const int m0 = blockIdx.y * BM, n0 = blockIdx.x * BN;
    const int NC = K >> 5;

    float acc[4][8][4];
#pragma unroll
    for (int a = 0; a < 4; ++a)
#pragma unroll
        for (int b = 0; b < 8; ++b)
#pragma unroll
            for (int c = 0; c < 4; ++c) acc[a][b][c] = 0.f;

    const int aRow = lane & 15;
    const int aKh = (lane >> 4) * 16;
    const int bRow = (lane & 7) + ((lane >> 4) << 3);
    const int bKh = ((lane >> 3) & 1) * 16;
    uint32_t aOff[4], bOff[4];
#pragma unroll
    for (int mb = 0; mb < 4; ++mb) aOff[mb] = (wm * 64 + mb * 16 + aRow) * ROWB + aKh;
#pragma unroll
    for (int pr = 0; pr < 4; ++pr) bOff[pr] = (wn * 64 + pr * 16 + bRow) * ROWB + bKh;

    // prologue: fill stages 0 and 1
#pragma unroll
    for (int c = 0; c < 2; ++c) {
        const uint32_t st = sb + c * STAGE;
        cpTile<BM>(st + OA_H, st + OA_L, Ah, Al, K, m0, c * BK, tid);
        cpTile<BN>(st + OB_H, st + OB_L, Bh, Bl, K, n0, c * BK, tid);
        asm volatile("cp.async.commit_group;" ::: "memory");
    }

    int sidx = 0;
    for (int c = 0; c < NC; ++c) {
        asm volatile("cp.async.wait_group 1;" ::: "memory");
        __syncthreads();
        // prefetch chunk c+2 into stage (c+2)%3 (last read at iter c-1 -> safe)
        if (c + 2 < NC) {
            int s2 = sidx + 2; if (s2 >= NSTAGE) s2 -= NSTAGE;
            const uint32_t nx = sb + s2 * STAGE;
            cpTile<BM>(nx + OA_H, nx + OA_L, Ah, Al, K, m0, (c + 2) * BK, tid);
            cpTile<BN>(nx + OB_H, nx + OB_L, Bh, Bl, K, n0, (c + 2) * BK, tid);
        }
        asm volatile("cp.async.commit_group;" ::: "memory");

        const uint32_t st = sb + sidx * STAGE;
#pragma unroll
        for (int ks = 0; ks < 2; ++ks) {
            uint32_t ah[4][4], al[4][4], bh[4][4], bl[4][4];
#pragma unroll
            for (int mb = 0; mb < 4; ++mb) {
                ldsm4(ah[mb], st + OA_H + aOff[mb] + ks * 32);
                ldsm4(al[mb], st + OA_L + aOff[mb] + ks * 32);
            }
#pragma unroll
            for (int pr = 0; pr < 4; ++pr) {
                ldsm4(bh[pr], st + OB_H + bOff[pr] + ks * 32);
                ldsm4(bl[pr], st + OB_L + bOff[pr] + ks * 32);
            }
#pragma unroll
            for (int mb = 0; mb < 4; ++mb)
#pragma unroll
                for (int nb = 0; nb < 8; ++nb) {
                    const uint32_t* fh = &bh[nb >> 1][(nb & 1) * 2];
                    const uint32_t* fl = &bl[nb >> 1][(nb & 1) * 2];
                    mma16816(acc[mb][nb], ah[mb], fh);
                    mma16816(acc[mb][nb], ah[mb], fl);
                    mma16816(acc[mb][nb], al[mb], fh);
                }
        }
        if (++sidx == NSTAGE) sidx = 0;
    }

    // ---------------- epilogue ----------------
    const int g = lane >> 2, tg = lane & 3;
#pragma unroll
    for (int mb = 0; mb < 4; ++mb) {
#pragma unroll
        for (int nb = 0; nb < 8; ++nb) {
            float* cc = acc[mb][nb];
            const int r0 = m0 + wm * 64 + mb * 16 + g;
            const int col = n0 + wn * 64 + nb * 8 + tg * 2;
            if (EPI == EPI_H1) {
                float bx = __ldg(bias + col), by = __ldg(bias + col + 1);
                float t0 = ftanh(cc[0] + bx), t1 = ftanh(cc[1] + by);
                float t2 = ftanh(cc[2] + bx), t3 = ftanh(cc[3] + by);
                split_store(P1h, P1l, (size_t)r0 * ldp + col, t0, t1);
                split_store(P1h, P1l, (size_t)(r0 + 8) * ldp + col, t2, t3);
            } else if (EPI == EPI_H2D2) {
                float bx = __ldg(bias + col), by = __ldg(bias + col + 1);
                float vx = __ldg(v3p + col), vy = __ldg(v3p + col + 1);
                float t0 = ftanh(cc[0] + bx), t1 = ftanh(cc[1] + by);
                float t2 = ftanh(cc[2] + bx), t3 = ftanh(cc[3] + by);
                split_store(P1h, P1l, (size_t)r0 * ldp + col, t0, t1);
                split_store(P1h, P1l, (size_t)(r0 + 8) * ldp + col, t2, t3);
                split_store(P2h, P2l, (size_t)r0 * ldp + col,
                            vx * (1.f - t0 * t0), vy * (1.f - t1 * t1));
                split_store(P2h, P2l, (size_t)(r0 + 8) * ldp + col,
                            vx * (1.f - t2 * t2), vy * (1.f - t3 * t3));
            } else if (EPI == EPI_OUT) {
                float bx = __ldg(bias + col), by = __ldg(bias + col + 1);
                C[(size_t)r0 * ldc + col]     = cc[0] + bx;
                C[(size_t)r0 * ldc + col + 1] = cc[1] + by;
                C[(size_t)(r0 + 8) * ldc + col]     = cc[2] + bx;
                C[(size_t)(r0 + 8) * ldc + col + 1] = cc[3] + by;
            } else if (EPI == EPI_D1) {
#pragma unroll
                for (int rr = 0; rr < 2; ++rr) {
                    size_t off = (size_t)(r0 + rr * 8) * ldp + col;
                    __nv_bfloat162 hh = *reinterpret_cast<const __nv_bfloat162*>(Xh + off);
                    __nv_bfloat162 hl = *reinterpret_cast<const __nv_bfloat162*>(Xl + off);
                    float h0 = __bfloat162float(hh.x) + __bfloat162float(hl.x);
                    float h1 = __bfloat162float(hh.y) + __bfloat162float(hl.y);
                    split_store(P1h, P1l, off,
                                cc[rr * 2] * (1.f - h0 * h0),
                                cc[rr * 2 + 1] * (1.f - h1 * h1));
                }
            } else {  // EPI_G
                *reinterpret_cast<float2*>(C + (size_t)r0 * ldc + col) =
                    make_float2(cc[0], cc[1]);
                *reinterpret_cast<float2*>(C + (size_t)(r0 + 8) * ldc + col) =
                    make_float2(cc[2], cc[3]);
            }
        }
    }
}

// ---------------- prep / misc kernels ----------------
__global__ void k_pack_z(const float* __restrict__ aug) {
    int b = blockIdx.x, t = threadIdx.x;
    float v = aug[(size_t)b * (DIM + 1) + t];
    __nv_bfloat16 h = __float2bfloat16(v);
    g_zh[(size_t)b * DIM + t] = h;
    g_zl[(size_t)b * DIM + t] = __float2bfloat16(v - __bfloat162float(h));
}

__global__ void k_split(const float* __restrict__ W, __nv_bfloat16* __restrict__ hi,
                        __nv_bfloat16* __restrict__ lo, int n) {
    int i = blockIdx.x * blockDim.x + threadIdx.x;
    if (i < n) {
        float v = W[i];
        __nv_bfloat16 h = __float2bfloat16(v);
        hi[i] = h;
        lo[i] = __float2bfloat16(v - __bfloat162float(h));
    }
}

// tiled transpose+split: out[n*K + k] = split(in[k*Nn + n]); grid (K/32, Nn/32), block (32,8)
__global__ void k_splitT(const float* __restrict__ in, __nv_bfloat16* __restrict__ hi,
                         __nv_bfloat16* __restrict__ lo, int K, int Nn) {
    __shared__ float t[32][33];
    int k0 = blockIdx.x * 32, n0 = blockIdx.y * 32;
    int tx = threadIdx.x, ty = threadIdx.y;
#pragma unroll
    for (int i = 0; i < 32; i += 8)
        t[ty + i][tx] = in[(size_t)(k0 + ty + i) * Nn + n0 + tx];
    __syncthreads();
#pragma unroll
    for (int i = 0; i < 32; i += 8) {
        float v = t[tx][ty + i];
        __nv_bfloat16 h = __float2bfloat16(v);
        size_t off = (size_t)(n0 + ty + i) * K + k0 + tx;
        hi[off] = h;
        lo[off] = __float2bfloat16(v - __bfloat162float(h));
    }
}

__global__ void k_v3(const float* __restrict__ W3) {
    int j = blockIdx.x * blockDim.x + threadIdx.x;
    float s = 0.f;
#pragma unroll 8
    for (int i = 0; i < DIM; ++i) s += W3[(size_t)i * HID + j];
    g_v3[j] = s;
}

__global__ void k_trace(const float* __restrict__ eps, float* __restrict__ out) {
    int gw = (blockIdx.x * blockDim.x + threadIdx.x) >> 5;
    int lane = threadIdx.x & 31;
    const float* g  = g_g + (size_t)gw * DIM;
    const float* e0 = eps + (size_t)gw * DIM;
    const float* e1 = eps + ((size_t)BATCH + gw) * DIM;
    const float* e2 = eps + ((size_t)2 * BATCH + gw) * DIM;
    float s = 0.f;
    for (int d = lane * 4; d < DIM; d += 128) {
        float4 gv = *(const float4*)(g + d);
        float4 a  = *(const float4*)(e0 + d);
        float4 b  = *(const float4*)(e1 + d);
        float4 c  = *(const float4*)(e2 + d);
        s += gv.x * (a.x + b.x + c.x) + gv.y * (a.y + b.y + c.y)
           + gv.z * (a.z + b.z + c.z) + gv.w * (a.w + b.w + c.w);
    }
#pragma unroll
    for (int off = 16; off; off >>= 1) s += __shfl_xor_sync(0xFFFFFFFFu, s, off);
    if (lane == 0) out[(size_t)gw * (DIM + 1) + DIM] = s * (1.f / 3.f);
}

// ---------------- launch ----------------
extern "C" void kernel_launch(void* const* d_in, const int* in_sizes, int n_in,
                              void* d_out, int out_size) {
    const float* aug = (const float*)d_in[1];
    const float* eps = (const float*)d_in[2];
    const float* W1  = (const float*)d_in[3];
    const float* b1  = (const float*)d_in[4];
    const float* W2  = (const float*)d_in[5];
    const float* b2  = (const float*)d_in[6];
    const float* W3  = (const float*)d_in[7];
    const float* b3  = (const float*)d_in[8];
    float* out = (float*)d_out;

    __nv_bfloat16 *zh, *zl, *h1h, *h1l, *h2h, *h2l, *d2h, *d2l, *d1h, *d1l;
    cudaGetSymbolAddress((void**)&zh,  g_zh);  cudaGetSymbolAddress((void**)&zl,  g_zl);
    cudaGetSymbolAddress((void**)&h1h, g_h1h); cudaGetSymbolAddress((void**)&h1l, g_h1l);
    cudaGetSymbolAddress((void**)&h2h, g_h2h); cudaGetSymbolAddress((void**)&h2l, g_h2l);
    cudaGetSymbolAddress((void**)&d2h, g_d2h); cudaGetSymbolAddress((void**)&d2l, g_d2l);
    cudaGetSymbolAddress((void**)&d1h, g_d1h); cudaGetSymbolAddress((void**)&d1l, g_d1l);
    float *gg, *v3p;
    cudaGetSymbolAddress((void**)&gg,  g_g);
    cudaGetSymbolAddress((void**)&v3p, g_v3);
    __nv_bfloat16 *w1h, *w1l, *w2h, *w2l, *w3h, *w3l, *w2th, *w2tl, *w1th, *w1tl;
    cudaGetSymbolAddress((void**)&w1h,  g_W1h);  cudaGetSymbolAddress((void**)&w1l,  g_W1l);
    cudaGetSymbolAddress((void**)&w2h,  g_W2h);  cudaGetSymbolAddress((void**)&w2l,  g_W2l);
    cudaGetSymbolAddress((void**)&w3h,  g_W3h);  cudaGetSymbolAddress((void**)&w3l,  g_W3l);
    cudaGetSymbolAddress((void**)&w2th, g_W2Th); cudaGetSymbolAddress((void**)&w2tl, g_W2Tl);
    cudaGetSymbolAddress((void**)&w1th, g_W1Th); cudaGetSymbolAddress((void**)&w1tl, g_W1Tl);

    cudaFuncSetAttribute(mma_gemm<EPI_H1>,   cudaFuncAttributeMaxDynamicSharedMemorySize, SMEM_TOTAL);
    cudaFuncSetAttribute(mma_gemm<EPI_H2D2>, cudaFuncAttributeMaxDynamicSharedMemorySize, SMEM_TOTAL);
    cudaFuncSetAttribute(mma_gemm<EPI_OUT>,  cudaFuncAttributeMaxDynamicSharedMemorySize, SMEM_TOTAL);
    cudaFuncSetAttribute(mma_gemm<EPI_D1>,   cudaFuncAttributeMaxDynamicSharedMemorySize, SMEM_TOTAL);
    cudaFuncSetAttribute(mma_gemm<EPI_G>,    cudaFuncAttributeMaxDynamicSharedMemorySize, SMEM_TOTAL);

    // prep
    k_pack_z<<<BATCH, DIM>>>(aug);
    k_split<<<(HID * DIM + 255) / 256, 256>>>(W1, w1h, w1l, HID * DIM);
    k_split<<<(HID * HID + 255) / 256, 256>>>(W2, w2h, w2l, HID * HID);
    k_split<<<(DIM * HID + 255) / 256, 256>>>(W3, w3h, w3l, DIM * HID);
    k_splitT<<<dim3(HID / 32, DIM / 32), dim3(32, 8)>>>(W1, w1th, w1tl, HID, DIM);
    k_splitT<<<dim3(HID / 32, HID / 32), dim3(32, 8)>>>(W2, w2th, w2tl, HID, HID);
    k_v3<<<HID / 256, 256>>>(W3);

    // G1: h1 = tanh(z @ W1^T + b1)   [K=512]
    mma_gemm<EPI_H1><<<dim3(HID / BN, BATCH / BM), THREADS, SMEM_TOTAL>>>(
        zh, zl, w1h, w1l, b1, nullptr, nullptr, 0,
        h1h, h1l, nullptr, nullptr, nullptr, nullptr, DIM, HID);
    // G2: h2 = tanh(h1 @ W2^T + b2); d2 = v3*(1-h2^2)
    mma_gemm<EPI_H2D2><<<dim3(HID / BN, BATCH / BM), THREADS, SMEM_TOTAL>>>(
        h1h, h1l, w2h, w2l, b2, v3p, nullptr, 0,
        h2h, h2l, d2h, d2l, nullptr, nullptr, HID, HID);
    // G3: dz_dt = h2 @ W3^T + b3 -> out[:, :512] (ldc=513)
    mma_gemm<EPI_OUT><<<dim3(DIM / BN, BATCH / BM), THREADS, SMEM_TOTAL>>>(
        h2h, h2l, w3h, w3l, b3, nullptr, out, DIM + 1,
        nullptr, nullptr, nullptr, nullptr, nullptr, nullptr, HID, 0);
    // G4: dh1 = d2 @ W2; d1 = dh1*(1-h1^2)
    mma_gemm<EPI_D1><<<dim3(HID / BN, BATCH / BM), THREADS, SMEM_TOTAL>>>(
        d2h, d2l, w2th, w2tl, nullptr, nullptr, nullptr, 0,
        d1h, d1l, nullptr, nullptr, h1h, h1l, HID, HID);
    // G5: g = d1 @ W1
    mma_gemm<EPI_G><<<dim3(DIM / BN, BATCH / BM), THREADS, SMEM_TOTAL>>>(
        d1h, d1l, w1th, w1tl, nullptr, nullptr, gg, DIM,
        nullptr, nullptr, nullptr, nullptr, nullptr, nullptr, HID, 0);

    k_trace<<<BATCH / 8, 256>>>(eps, out);
}

// round 6
// speedup vs baseline: 1.0449x; 1.0449x over previous
#include <cuda_runtime.h>
#include <cuda_bf16.h>
#include <math.h>
#include <stdint.h>

#define BATCH 16384
#define DIM   512
#define HID   2048

#define BM 128
#define BN 128
#define BK 32
#define THREADS 256

// smem rows padded to 80B (32 bf16 + 16B pad): conflict-free ldmatrix phases
#define ROWB   80
#define OA_H   0
#define OA_L   10240
#define OB_H   20480
#define OB_L   30720
#define STAGE  40960
#define SMEM_TOTAL (2 * STAGE)

// ---------------- scratch (allocation-free) ----------------
__device__ __nv_bfloat16 g_zh[(size_t)BATCH * DIM],  g_zl[(size_t)BATCH * DIM];
__device__ __nv_bfloat16 g_h1h[(size_t)BATCH * HID], g_h1l[(size_t)BATCH * HID];
__device__ __nv_bfloat16 g_h2h[(size_t)BATCH * HID], g_h2l[(size_t)BATCH * HID];
__device__ __nv_bfloat16 g_d2h[(size_t)BATCH * HID], g_d2l[(size_t)BATCH * HID];
__device__ __nv_bfloat16 g_d1h[(size_t)BATCH * HID], g_d1l[(size_t)BATCH * HID];
__device__ float g_g[(size_t)BATCH * DIM];
__device__ float g_v3[HID];
__device__ __nv_bfloat16 g_W1h[HID * DIM],  g_W1l[HID * DIM];
__device__ __nv_bfloat16 g_W2h[HID * HID],  g_W2l[HID * HID];
__device__ __nv_bfloat16 g_W3h[DIM * HID],  g_W3l[DIM * HID];
__device__ __nv_bfloat16 g_W2Th[HID * HID], g_W2Tl[HID * HID];
__device__ __nv_bfloat16 g_W1Th[DIM * HID], g_W1Tl[DIM * HID];

enum { EPI_H1 = 0, EPI_H2D2 = 1, EPI_OUT = 2, EPI_D1 = 3, EPI_G = 4 };

// ---------------- helpers ----------------
__device__ __forceinline__ uint32_t s2u(const void* p) {
    uint32_t a;
    asm("{ .reg .u64 t; cvta.to.shared.u64 t, %1; cvt.u32.u64 %0, t; }" : "=r"(a) : "l"(p));
    return a;
}

__device__ __forceinline__ void ldsm4(uint32_t* r, uint32_t addr) {
    asm volatile("ldmatrix.sync.aligned.m8n8.x4.shared.b16 {%0,%1,%2,%3}, [%4];"
                 : "=r"(r[0]), "=r"(r[1]), "=r"(r[2]), "=r"(r[3]) : "r"(addr));
}

__device__ __forceinline__ void mma16816(float* c, const uint32_t* a, const uint32_t* b) {
    asm volatile("mma.sync.aligned.m16n8k16.row.col.f32.bf16.bf16.f32 "
                 "{%0,%1,%2,%3}, {%4,%5,%6,%7}, {%8,%9}, {%0,%1,%2,%3};"
                 : "+f"(c[0]), "+f"(c[1]), "+f"(c[2]), "+f"(c[3])
                 : "r"(a[0]), "r"(a[1]), "r"(a[2]), "r"(a[3]), "r"(b[0]), "r"(b[1]));
}

__device__ __forceinline__ void cp16(uint32_t dst, const void* src) {
    asm volatile("cp.async.cg.shared.global [%0], [%1], 16;" :: "r"(dst), "l"(src) : "memory");
}

__device__ __forceinline__ float ftanh(float x) {
    float e = __expf(2.f * x);
    return 1.f - __fdividef(2.f, e + 1.f);
}

__device__ __forceinline__ void split_store(__nv_bfloat16* __restrict__ H,
                                            __nv_bfloat16* __restrict__ L,
                                            size_t off, float x, float y) {
    __nv_bfloat162 h = __floats2bfloat162_rn(x, y);
    __nv_bfloat162 l = __floats2bfloat162_rn(x - __bfloat162float(h.x),
                                             y - __bfloat162float(h.y));
    *reinterpret_cast<__nv_bfloat162*>(H + off) = h;
    *reinterpret_cast<__nv_bfloat162*>(L + off) = l;
}

// tile: 128 rows x 32 cols bf16 hi+lo via cp.async (4 transfers/thread)
__device__ __forceinline__ void cpTile(uint32_t dstH, uint32_t dstL,
                                       const __nv_bfloat16* __restrict__ srcH,
                                       const __nv_bfloat16* __restrict__ srcL,
                                       int ld, int r0, int k0, int tid) {
#pragma unroll
    for (int i = 0; i < 2; ++i) {
        int idx = tid + i * 256;
        int row = idx >> 2, seg = idx & 3;
        size_t go = (size_t)(r0 + row) * ld + k0 + seg * 8;
        uint32_t so = row * ROWB + seg * 16;
        cp16(dstH + so, srcH + go);
        cp16(dstL + so, srcL + go);
    }
}

// ---------------- split-bf16 warp-MMA GEMM (R4 config: 128x128, 2 CTA/SM) ----------------
template <int EPI>
__global__ void __launch_bounds__(THREADS, 2) mma_gemm(
    const __nv_bfloat16* __restrict__ Ah, const __nv_bfloat16* __restrict__ Al,
    const __nv_bfloat16* __restrict__ Bh, const __nv_bfloat16* __restrict__ Bl,
    const float* __restrict__ bias, const float* __restrict__ v3p,
    float* __restrict__ C, int ldc,
    __nv_bfloat16* __restrict__ P1h, __nv_bfloat16* __restrict__ P1l,
    __nv_bfloat16* __restrict__ P2h, __nv_bfloat16* __restrict__ P2l,
    const __nv_bfloat16* __restrict__ Xh, const __nv_bfloat16* __restrict__ Xl,
    int K, int ldp)
{
    extern __shared__ char smem[];
    const uint32_t sb = s2u(smem);
    const int tid = threadIdx.x, lane = tid & 31, wid = tid >> 5;
    const int wm = wid >> 2, wn = wid & 3;           // 2x4 warps, 64x32 each
    const int m0 = blockIdx.y * BM, n0 = blockIdx.x * BN;
    const int NC = K >> 5;

    float acc[4][4][4];
#pragma unroll
    for (int a = 0; a < 4; ++a)
#pragma unroll
        for (int b = 0; b < 4; ++b)
#pragma unroll
            for (int c = 0; c < 4; ++c) acc[a][b][c] = 0.f;

    const int aRow = lane & 15;
    const int aKh = (lane >> 4) * 16;
    const int bRow = (lane & 7) + ((lane >> 4) << 3);
    const int bKh = ((lane >> 3) & 1) * 16;
    uint32_t aOff[4], bOff[2];
#pragma unroll
    for (int mb = 0; mb < 4; ++mb) aOff[mb] = (wm * 64 + mb * 16 + aRow) * ROWB + aKh;
#pragma unroll
    for (int pr = 0; pr < 2; ++pr) bOff[pr] = (wn * 32 + pr * 16 + bRow) * ROWB + bKh;

    // prologue: chunk 0 -> stage 0
    cpTile(sb + OA_H, sb + OA_L, Ah, Al, K, m0, 0, tid);
    cpTile(sb + OB_H, sb + OB_L, Bh, Bl, K, n0, 0, tid);
    asm volatile("cp.async.commit_group;" ::: "memory");

    for (int c = 0; c < NC; ++c) {
        const int s = c & 1;
        const uint32_t st = sb + s * STAGE;
        __syncthreads();   // everyone done reading stage s^1 (iter c-1)
        if (c + 1 < NC) {
            const uint32_t nx = sb + (s ^ 1) * STAGE;
            cpTile(nx + OA_H, nx + OA_L, Ah, Al, K, m0, (c + 1) * BK, tid);
            cpTile(nx + OB_H, nx + OB_L, Bh, Bl, K, n0, (c + 1) * BK, tid);
        }
        asm volatile("cp.async.commit_group;" ::: "memory");
        asm volatile("cp.async.wait_group 1;" ::: "memory");
        __syncthreads();   // chunk c visible

#pragma unroll
        for (int ks = 0; ks < 2; ++ks) {
            uint32_t ah[4][4], al[4][4], bh[2][4], bl[2][4];
#pragma unroll
            for (int mb = 0; mb < 4; ++mb) ldsm4(ah[mb], st + OA_H + aOff[mb] + ks * 32);
#pragma unroll
            for (int mb = 0; mb < 4; ++mb) ldsm4(al[mb], st + OA_L + aOff[mb] + ks * 32);
#pragma unroll
            for (int pr = 0; pr < 2; ++pr) ldsm4(bh[pr], st + OB_H + bOff[pr] + ks * 32);
#pragma unroll
            for (int pr = 0; pr < 2; ++pr) ldsm4(bl[pr], st + OB_L + bOff[pr] + ks * 32);
#pragma unroll
            for (int mb = 0; mb < 4; ++mb)
#pragma unroll
                for (int nb = 0; nb < 4; ++nb) {
                    const uint32_t* fh = &bh[nb >> 1][(nb & 1) * 2];
                    const uint32_t* fl = &bl[nb >> 1][(nb & 1) * 2];
                    mma16816(acc[mb][nb], ah[mb], fh);
                    mma16816(acc[mb][nb], ah[mb], fl);
                    mma16816(acc[mb][nb], al[mb], fh);
                }
        }
    }

    // ---------------- epilogue ----------------
    const int g = lane >> 2, tg = lane & 3;
#pragma unroll
    for (int mb = 0; mb < 4; ++mb) {
#pragma unroll
        for (int nb = 0; nb < 4; ++nb) {
            float* cc = acc[mb][nb];
            const int r0 = m0 + wm * 64 + mb * 16 + g;
            const int col = n0 + wn * 32 + nb * 8 + tg * 2;
            if (EPI == EPI_H1) {
                float bx = __ldg(bias + col), by = __ldg(bias + col + 1);
                float t0 = ftanh(cc[0] + bx), t1 = ftanh(cc[1] + by);
                float t2 = ftanh(cc[2] + bx), t3 = ftanh(cc[3] + by);
                split_store(P1h, P1l, (size_t)r0 * ldp + col, t0, t1);
                split_store(P1h, P1l, (size_t)(r0 + 8) * ldp + col, t2, t3);
            } else if (EPI == EPI_H2D2) {
                float bx = __ldg(bias + col), by = __ldg(bias + col + 1);
                float vx = __ldg(v3p + col), vy = __ldg(v3p + col + 1);
                float t0 = ftanh(cc[0] + bx), t1 = ftanh(cc[1] + by);
                float t2 = ftanh(cc[2] + bx), t3 = ftanh(cc[3] + by);
                split_store(P1h, P1l, (size_t)r0 * ldp + col, t0, t1);
                split_store(P1h, P1l, (size_t)(r0 + 8) * ldp + col, t2, t3);
                split_store(P2h, P2l, (size_t)r0 * ldp + col,
                            vx * (1.f - t0 * t0), vy * (1.f - t1 * t1));
                split_store(P2h, P2l, (size_t)(r0 + 8) * ldp + col,
                            vx * (1.f - t2 * t2), vy * (1.f - t3 * t3));
            } else if (EPI == EPI_OUT) {
                float bx = __ldg(bias + col), by = __ldg(bias + col + 1);
                C[(size_t)r0 * ldc + col]     = cc[0] + bx;
                C[(size_t)r0 * ldc + col + 1] = cc[1] + by;
                C[(size_t)(r0 + 8) * ldc + col]     = cc[2] + bx;
                C[(size_t)(r0 + 8) * ldc + col + 1] = cc[3] + by;
            } else if (EPI == EPI_D1) {
#pragma unroll
                for (int rr = 0; rr < 2; ++rr) {
                    size_t off = (size_t)(r0 + rr * 8) * ldp + col;
                    __nv_bfloat162 hh = *reinterpret_cast<const __nv_bfloat162*>(Xh + off);
                    __nv_bfloat162 hl = *reinterpret_cast<const __nv_bfloat162*>(Xl + off);
                    float h0 = __bfloat162float(hh.x) + __bfloat162float(hl.x);
                    float h1 = __bfloat162float(hh.y) + __bfloat162float(hl.y);
                    split_store(P1h, P1l, off,
                                cc[rr * 2] * (1.f - h0 * h0),
                                cc[rr * 2 + 1] * (1.f - h1 * h1));
                }
            } else {  // EPI_G
                *reinterpret_cast<float2*>(C + (size_t)r0 * ldc + col) =
                    make_float2(cc[0], cc[1]);
                *reinterpret_cast<float2*>(C + (size_t)(r0 + 8) * ldc + col) =
                    make_float2(cc[2], cc[3]);
            }
        }
    }
}

// ---------------- merged prep kernel (one launch, segmented grid) ----------------
// segments (blocks of 256 threads):
//  [0, 4096)            : split W1          (1M elems, 256/blk)
//  [4096, 20480)        : split W2          (4M)
//  [20480, 24576)       : split W3          (1M)
//  [24576, 25600)       : transpose-split W1 -> W1T  (grid 64x16 tiles)
//  [25600, 29696)       : transpose-split W2 -> W2T  (grid 64x64 tiles)
//  [29696, 29704)       : v3 colsum of W3   (8 blocks)
#define PB_W1   4096
#define PB_W2   (PB_W1 + 16384)
#define PB_W3   (PB_W2 + 4096)
#define PB_W1T  (PB_W3 + 1024)
#define PB_W2T  (PB_W1T + 4096)
#define PB_V3   (PB_W2T + 8)

__device__ __forceinline__ void seg_split(const float* __restrict__ W,
                                          __nv_bfloat16* __restrict__ hi,
                                          __nv_bfloat16* __restrict__ lo,
                                          int base, int tid) {
    int i = base * 256 + tid;
    float v = W[i];
    __nv_bfloat16 h = __float2bfloat16(v);
    hi[i] = h;
    lo[i] = __float2bfloat16(v - __bfloat162float(h));
}

__device__ __forceinline__ void seg_splitT(const float* __restrict__ in,
                                           __nv_bfloat16* __restrict__ hi,
                                           __nv_bfloat16* __restrict__ lo,
                                           int K, int Nn, int tileIdx, int tid) {
    __shared__ float t[32][33];
    int tilesX = K / 32;
    int k0 = (tileIdx % tilesX) * 32, n0 = (tileIdx / tilesX) * 32;
    int tx = tid & 31, ty = tid >> 5;
#pragma unroll
    for (int i = 0; i < 32; i += 8)
        t[ty + i][tx] = in[(size_t)(k0 + ty + i) * Nn + n0 + tx];
    __syncthreads();
#pragma unroll
    for (int i = 0; i < 32; i += 8) {
        float v = t[tx][ty + i];
        __nv_bfloat16 h = __float2bfloat16(v);
        size_t off = (size_t)(n0 + ty + i) * K + k0 + tx;
        hi[off] = h;
        lo[off] = __float2bfloat16(v - __bfloat162float(h));
    }
}

__global__ void __launch_bounds__(256) k_prep(const float* __restrict__ W1,
                                              const float* __restrict__ W2,
                                              const float* __restrict__ W3) {
    int b = blockIdx.x, tid = threadIdx.x;
    if (b < PB_W1) {
        seg_split(W1, g_W1h, g_W1l, b, tid);
    } else if (b < PB_W2) {
        seg_split(W2, g_W2h, g_W2l, b - PB_W1, tid);
    } else if (b < PB_W3) {
        seg_split(W3, g_W3h, g_W3l, b - PB_W2, tid);
    } else if (b < PB_W1T) {
        seg_splitT(W1, g_W1Th, g_W1Tl, HID, DIM, b - PB_W3, tid);
    } else if (b < PB_W2T) {
        seg_splitT(W2, g_W2Th, g_W2Tl, HID, HID, b - PB_W1T, tid);
    } else {
        int j = (b - PB_W2T) * 256 + tid;
        float s = 0.f;
#pragma unroll 8
        for (int i = 0; i < DIM; ++i) s += W3[(size_t)i * HID + j];
        g_v3[j] = s;
    }
}

__global__ void k_pack_z(const float* __restrict__ aug) {
    int b = blockIdx.x, t = threadIdx.x;
    float v = aug[(size_t)b * (DIM + 1) + t];
    __nv_bfloat16 h = __float2bfloat16(v);
    g_zh[(size_t)b * DIM + t] = h;
    g_zl[(size_t)b * DIM + t] = __float2bfloat16(v - __bfloat162float(h));
}

__global__ void k_trace(const float* __restrict__ eps, float* __restrict__ out) {
    int gw = (blockIdx.x * blockDim.x + threadIdx.x) >> 5;
    int lane = threadIdx.x & 31;
    const float* g  = g_g + (size_t)gw * DIM;
    const float* e0 = eps + (size_t)gw * DIM;
    const float* e1 = eps + ((size_t)BATCH + gw) * DIM;
    const float* e2 = eps + ((size_t)2 * BATCH + gw) * DIM;
    float s = 0.f;
    for (int d = lane * 4; d < DIM; d += 128) {
        float4 gv = *(const float4*)(g + d);
        float4 a  = *(const float4*)(e0 + d);
        float4 b  = *(const float4*)(e1 + d);
        float4 c  = *(const float4*)(e2 + d);
        s += gv.x * (a.x + b.x + c.x) + gv.y * (a.y + b.y + c.y)
           + gv.z * (a.z + b.z + c.z) + gv.w * (a.w + b.w + c.w);
    }
#pragma unroll
    for (int off = 16; off; off >>= 1) s += __shfl_xor_sync(0xFFFFFFFFu, s, off);
    if (lane == 0) out[(size_t)gw * (DIM + 1) + DIM] = s * (1.f / 3.f);
}

// ---------------- launch ----------------
extern "C" void kernel_launch(void* const* d_in, const int* in_sizes, int n_in,
                              void* d_out, int out_size) {
    const float* aug = (const float*)d_in[1];
    const float* eps = (const float*)d_in[2];
    const float* W1  = (const float*)d_in[3];
    const float* b1  = (const float*)d_in[4];
    const float* W2  = (const float*)d_in[5];
    const float* b2  = (const float*)d_in[6];
    const float* W3  = (const float*)d_in[7];
    const float* b3  = (const float*)d_in[8];
    float* out = (float*)d_out;

    __nv_bfloat16 *zh, *zl, *h1h, *h1l, *h2h, *h2l, *d2h, *d2l, *d1h, *d1l;
    cudaGetSymbolAddress((void**)&zh,  g_zh);  cudaGetSymbolAddress((void**)&zl,  g_zl);
    cudaGetSymbolAddress((void**)&h1h, g_h1h); cudaGetSymbolAddress((void**)&h1l, g_h1l);
    cudaGetSymbolAddress((void**)&h2h, g_h2h); cudaGetSymbolAddress((void**)&h2l, g_h2l);
    cudaGetSymbolAddress((void**)&d2h, g_d2h); cudaGetSymbolAddress((void**)&d2l, g_d2l);
    cudaGetSymbolAddress((void**)&d1h, g_d1h); cudaGetSymbolAddress((void**)&d1l, g_d1l);
    float *gg, *v3p;
    cudaGetSymbolAddress((void**)&gg,  g_g);
    cudaGetSymbolAddress((void**)&v3p, g_v3);
    __nv_bfloat16 *w1h, *w1l, *w2h, *w2l, *w3h, *w3l, *w2th, *w2tl, *w1th, *w1tl;
    cudaGetSymbolAddress((void**)&w1h,  g_W1h);  cudaGetSymbolAddress((void**)&w1l,  g_W1l);
    cudaGetSymbolAddress((void**)&w2h,  g_W2h);  cudaGetSymbolAddress((void**)&w2l,  g_W2l);
    cudaGetSymbolAddress((void**)&w3h,  g_W3h);  cudaGetSymbolAddress((void**)&w3l,  g_W3l);
    cudaGetSymbolAddress((void**)&w2th, g_W2Th); cudaGetSymbolAddress((void**)&w2tl, g_W2Tl);
    cudaGetSymbolAddress((void**)&w1th, g_W1Th); cudaGetSymbolAddress((void**)&w1tl, g_W1Tl);

    cudaFuncSetAttribute(mma_gemm<EPI_H1>,   cudaFuncAttributeMaxDynamicSharedMemorySize, SMEM_TOTAL);
    cudaFuncSetAttribute(mma_gemm<EPI_H2D2>, cudaFuncAttributeMaxDynamicSharedMemorySize, SMEM_TOTAL);
    cudaFuncSetAttribute(mma_gemm<EPI_OUT>,  cudaFuncAttributeMaxDynamicSharedMemorySize, SMEM_TOTAL);
    cudaFuncSetAttribute(mma_gemm<EPI_D1>,   cudaFuncAttributeMaxDynamicSharedMemorySize, SMEM_TOTAL);
    cudaFuncSetAttribute(mma_gemm<EPI_G>,    cudaFuncAttributeMaxDynamicSharedMemorySize, SMEM_TOTAL);

    // launch 0: all weight prep in one grid
    k_prep<<<PB_V3, 256>>>(W1, W2, W3);
    // launch 1: activation pack/split
    k_pack_z<<<BATCH, DIM>>>(aug);

    // launch 2 — G1: h1 = tanh(z @ W1^T + b1)   [K=512]
    mma_gemm<EPI_H1><<<dim3(HID / BN, BATCH / BM), THREADS, SMEM_TOTAL>>>(
        zh, zl, w1h, w1l, b1, nullptr, nullptr, 0,
        h1h, h1l, nullptr, nullptr, nullptr, nullptr, DIM, HID);
    // launch 3 — G2: h2 = tanh(h1 @ W2^T + b2); d2 = v3*(1-h2^2)
    mma_gemm<EPI_H2D2><<<dim3(HID / BN, BATCH / BM), THREADS, SMEM_TOTAL>>>(
        h1h, h1l, w2h, w2l, b2, v3p, nullptr, 0,
        h2h, h2l, d2h, d2l, nullptr, nullptr, HID, HID);
    // launch 4 — G3: dz_dt = h2 @ W3^T + b3 -> out[:, :512] (ldc=513)
    mma_gemm<EPI_OUT><<<dim3(DIM / BN, BATCH / BM), THREADS, SMEM_TOTAL>>>(
        h2h, h2l, w3h, w3l, b3, nullptr, out, DIM + 1,
        nullptr, nullptr, nullptr, nullptr, nullptr, nullptr, HID, 0);
    // launch 5 — G4: dh1 = d2 @ W2; d1 = dh1*(1-h1^2)   <-- ncu -s 5 captures this
    mma_gemm<EPI_D1><<<dim3(HID / BN, BATCH / BM), THREADS, SMEM_TOTAL>>>(
        d2h, d2l, w2th, w2tl, nullptr, nullptr, nullptr, 0,
        d1h, d1l, nullptr, nullptr, h1h, h1l, HID, HID);
    // launch 6 — G5: g = d1 @ W1
    mma_gemm<EPI_G><<<dim3(DIM / BN, BATCH / BM), THREADS, SMEM_TOTAL>>>(
        d1h, d1l, w1th, w1tl, nullptr, nullptr, gg, DIM,
        nullptr, nullptr, nullptr, nullptr, nullptr, nullptr, HID, 0);

    // launch 7 — trace column
    k_trace<<<BATCH / 8, 256>>>(eps, out);
}

// round 7
// speedup vs baseline: 1.0898x; 1.0430x over previous
#include <cuda_runtime.h>
#include <cuda_bf16.h>
#include <math.h>
#include <stdint.h>

#define BATCH 16384
#define DIM   512
#define HID   2048

#define BM 128
#define BN 128
#define BK 32
#define THREADS 256

// smem: 64B rows (32 bf16), XOR-swizzled 16B chunks -> conflict-free ldsm + STS
#define OA_H   0
#define OA_L   8192
#define OB_H   16384
#define OB_L   24576
#define STAGE  32768
#define NSTAGE 3
#define SMEM_TOTAL (NSTAGE * STAGE)   // 98304 -> 2 CTAs/SM (192KB of 227KB)

// ---------------- scratch (allocation-free) ----------------
__device__ __nv_bfloat16 g_zh[(size_t)BATCH * DIM],  g_zl[(size_t)BATCH * DIM];
__device__ __nv_bfloat16 g_h1h[(size_t)BATCH * HID], g_h1l[(size_t)BATCH * HID];
__device__ __nv_bfloat16 g_h2h[(size_t)BATCH * HID], g_h2l[(size_t)BATCH * HID];
__device__ __nv_bfloat16 g_d2h[(size_t)BATCH * HID], g_d2l[(size_t)BATCH * HID];
__device__ __nv_bfloat16 g_d1h[(size_t)BATCH * HID], g_d1l[(size_t)BATCH * HID];
__device__ float g_g[(size_t)BATCH * DIM];
__device__ float g_v3[HID];
__device__ __nv_bfloat16 g_W1h[HID * DIM],  g_W1l[HID * DIM];
__device__ __nv_bfloat16 g_W2h[HID * HID],  g_W2l[HID * HID];
__device__ __nv_bfloat16 g_W3h[DIM * HID],  g_W3l[DIM * HID];
__device__ __nv_bfloat16 g_W2Th[HID * HID], g_W2Tl[HID * HID];
__device__ __nv_bfloat16 g_W1Th[DIM * HID], g_W1Tl[DIM * HID];

enum { EPI_H1 = 0, EPI_H2D2 = 1, EPI_OUT = 2, EPI_D1 = 3, EPI_G = 4 };

// ---------------- helpers ----------------
__device__ __forceinline__ uint32_t s2u(const void* p) {
    uint32_t a;
    asm("{ .reg .u64 t; cvta.to.shared.u64 t, %1; cvt.u32.u64 %0, t; }" : "=r"(a) : "l"(p));
    return a;
}

// swizzled byte offset within a 128x32 bf16 tile: 64B rows, 16B chunk rotate by row>>1
__device__ __forceinline__ uint32_t swoff(int row, int seg) {
    return (uint32_t)(row * 64 + (((seg + (row >> 1)) & 3) << 4));
}

__device__ __forceinline__ void ldsm4(uint32_t* r, uint32_t addr) {
    asm volatile("ldmatrix.sync.aligned.m8n8.x4.shared.b16 {%0,%1,%2,%3}, [%4];"
                 : "=r"(r[0]), "=r"(r[1]), "=r"(r[2]), "=r"(r[3]) : "r"(addr));
}

__device__ __forceinline__ void mma16816(float* c, const uint32_t* a, const uint32_t* b) {
    asm volatile("mma.sync.aligned.m16n8k16.row.col.f32.bf16.bf16.f32 "
                 "{%0,%1,%2,%3}, {%4,%5,%6,%7}, {%8,%9}, {%0,%1,%2,%3};"
                 : "+f"(c[0]), "+f"(c[1]), "+f"(c[2]), "+f"(c[3])
                 : "r"(a[0]), "r"(a[1]), "r"(a[2]), "r"(a[3]), "r"(b[0]), "r"(b[1]));
}

__device__ __forceinline__ void cp16(uint32_t dst, const void* src) {
    asm volatile("cp.async.cg.shared.global [%0], [%1], 16;" :: "r"(dst), "l"(src) : "memory");
}

__device__ __forceinline__ float ftanh(float x) {
    float e = __expf(2.f * x);
    return 1.f - __fdividef(2.f, e + 1.f);
}

__device__ __forceinline__ void split_store(__nv_bfloat16* __restrict__ H,
                                            __nv_bfloat16* __restrict__ L,
                                            size_t off, float x, float y) {
    __nv_bfloat162 h = __floats2bfloat162_rn(x, y);
    __nv_bfloat162 l = __floats2bfloat162_rn(x - __bfloat162float(h.x),
                                             y - __bfloat162float(h.y));
    *reinterpret_cast<__nv_bfloat162*>(H + off) = h;
    *reinterpret_cast<__nv_bfloat162*>(L + off) = l;
}

// tile: 128 rows x 32 cols bf16 hi+lo via cp.async into swizzled smem
__device__ __forceinline__ void cpTile(uint32_t dstH, uint32_t dstL,
                                       const __nv_bfloat16* __restrict__ srcH,
                                       const __nv_bfloat16* __restrict__ srcL,
                                       int ld, int r0, int k0, int tid) {
#pragma unroll
    for (int i = 0; i < 2; ++i) {
        int idx = tid + i * 256;
        int row = idx >> 2, seg = idx & 3;
        size_t go = (size_t)(r0 + row) * ld + k0 + seg * 8;
        uint32_t so = swoff(row, seg);
        cp16(dstH + so, srcH + go);
        cp16(dstL + so, srcL + go);
    }
}

// ---------------- split-bf16 warp-MMA GEMM: 128x128 tile, 3-stage, 1 barrier ----------------
template <int EPI>
__global__ void __launch_bounds__(THREADS, 2) mma_gemm(
    const __nv_bfloat16* __restrict__ Ah, const __nv_bfloat16* __restrict__ Al,
    const __nv_bfloat16* __restrict__ Bh, const __nv_bfloat16* __restrict__ Bl,
    const float* __restrict__ bias, const float* __restrict__ v3p,
    float* __restrict__ C, int ldc,
    __nv_bfloat16* __restrict__ P1h, __nv_bfloat16* __restrict__ P1l,
    __nv_bfloat16* __restrict__ P2h, __nv_bfloat16* __restrict__ P2l,
    const __nv_bfloat16* __restrict__ Xh, const __nv_bfloat16* __restrict__ Xl,
    int K, int ldp)
{
    extern __shared__ char smem[];
    const uint32_t sb = s2u(smem);
    const int tid = threadIdx.x, lane = tid & 31, wid = tid >> 5;
    const int wm = wid >> 2, wn = wid & 3;           // 2x4 warps, 64x32 each
    const int m0 = blockIdx.y * BM, n0 = blockIdx.x * BN;
    const int NC = K >> 5;                           // >= 16

    float acc[4][4][4];
#pragma unroll
    for (int a = 0; a < 4; ++a)
#pragma unroll
        for (int b = 0; b < 4; ++b)
#pragma unroll
            for (int c = 0; c < 4; ++c) acc[a][b][c] = 0.f;

    // swizzled fragment base offsets (ks half toggles bit 5 via XOR)
    const int aRow = lane & 15;
    const int bRow = (lane & 7) + ((lane >> 4) << 3);
    uint32_t aBase[4], bBase[2];
#pragma unroll
    for (int mb = 0; mb < 4; ++mb)
        aBase[mb] = swoff(wm * 64 + mb * 16 + aRow, lane >> 4);
#pragma unroll
    for (int pr = 0; pr < 2; ++pr)
        bBase[pr] = swoff(wn * 32 + pr * 16 + bRow, (lane >> 3) & 1);

    // prologue: chunks 0,1 -> stages 0,1
#pragma unroll
    for (int c = 0; c < 2; ++c) {
        const uint32_t st = sb + c * STAGE;
        cpTile(st + OA_H, st + OA_L, Ah, Al, K, m0, c * BK, tid);
        cpTile(st + OB_H, st + OB_L, Bh, Bl, K, n0, c * BK, tid);
        asm volatile("cp.async.commit_group;" ::: "memory");
    }

    int sidx = 0;
    for (int c = 0; c < NC; ++c) {
        asm volatile("cp.async.wait_group 1;" ::: "memory");  // chunk c arrived
        __syncthreads();                                      // visibility + WAR (dist-2 write)
        if (c + 2 < NC) {
            int s2 = sidx + 2; if (s2 >= NSTAGE) s2 -= NSTAGE;
            const uint32_t nx = sb + s2 * STAGE;
            cpTile(nx + OA_H, nx + OA_L, Ah, Al, K, m0, (c + 2) * BK, tid);
            cpTile(nx + OB_H, nx + OB_L, Bh, Bl, K, n0, (c + 2) * BK, tid);
        }
        asm volatile("cp.async.commit_group;" ::: "memory");

        const uint32_t st = sb + sidx * STAGE;
#pragma unroll
        for (int ks = 0; ks < 2; ++ks) {
            const uint32_t kx = ks << 5;
            uint32_t ah[4][4], al[4][4], bh[2][4], bl[2][4];
#pragma unroll
            for (int mb = 0; mb < 4; ++mb) ldsm4(ah[mb], st + OA_H + (aBase[mb] ^ kx));
#pragma unroll
            for (int mb = 0; mb < 4; ++mb) ldsm4(al[mb], st + OA_L + (aBase[mb] ^ kx));
#pragma unroll
            for (int pr = 0; pr < 2; ++pr) ldsm4(bh[pr], st + OB_H + (bBase[pr] ^ kx));
#pragma unroll
            for (int pr = 0; pr < 2; ++pr) ldsm4(bl[pr], st + OB_L + (bBase[pr] ^ kx));
#pragma unroll
            for (int mb = 0; mb < 4; ++mb)
#pragma unroll
                for (int nb = 0; nb < 4; ++nb) {
                    const uint32_t* fh = &bh[nb >> 1][(nb & 1) * 2];
                    const uint32_t* fl = &bl[nb >> 1][(nb & 1) * 2];
                    mma16816(acc[mb][nb], ah[mb], fh);
                    mma16816(acc[mb][nb], ah[mb], fl);
                    mma16816(acc[mb][nb], al[mb], fh);
                }
        }
        if (++sidx == NSTAGE) sidx = 0;
    }

    // ---------------- epilogue ----------------
    const int g = lane >> 2, tg = lane & 3;
#pragma unroll
    for (int mb = 0; mb < 4; ++mb) {
#pragma unroll
        for (int nb = 0; nb < 4; ++nb) {
            float* cc = acc[mb][nb];
            const int r0 = m0 + wm * 64 + mb * 16 + g;
            const int col = n0 + wn * 32 + nb * 8 + tg * 2;
            if (EPI == EPI_H1) {
                float bx = __ldg(bias + col), by = __ldg(bias + col + 1);
                float t0 = ftanh(cc[0] + bx), t1 = ftanh(cc[1] + by);
                float t2 = ftanh(cc[2] + bx), t3 = ftanh(cc[3] + by);
                split_store(P1h, P1l, (size_t)r0 * ldp + col, t0, t1);
                split_store(P1h, P1l, (size_t)(r0 + 8) * ldp + col, t2, t3);
            } else if (EPI == EPI_H2D2) {
                float bx = __ldg(bias + col), by = __ldg(bias + col + 1);
                float vx = __ldg(v3p + col), vy = __ldg(v3p + col + 1);
                float t0 = ftanh(cc[0] + bx), t1 = ftanh(cc[1] + by);
                float t2 = ftanh(cc[2] + bx), t3 = ftanh(cc[3] + by);
                split_store(P1h, P1l, (size_t)r0 * ldp + col, t0, t1);
                split_store(P1h, P1l, (size_t)(r0 + 8) * ldp + col, t2, t3);
                split_store(P2h, P2l, (size_t)r0 * ldp + col,
                            vx * (1.f - t0 * t0), vy * (1.f - t1 * t1));
                split_store(P2h, P2l, (size_t)(r0 + 8) * ldp + col,
                            vx * (1.f - t2 * t2), vy * (1.f - t3 * t3));
            } else if (EPI == EPI_OUT) {
                float bx = __ldg(bias + col), by = __ldg(bias + col + 1);
                C[(size_t)r0 * ldc + col]     = cc[0] + bx;
                C[(size_t)r0 * ldc + col + 1] = cc[1] + by;
                C[(size_t)(r0 + 8) * ldc + col]     = cc[2] + bx;
                C[(size_t)(r0 + 8) * ldc + col + 1] = cc[3] + by;
            } else if (EPI == EPI_D1) {
#pragma unroll
                for (int rr = 0; rr < 2; ++rr) {
                    size_t off = (size_t)(r0 + rr * 8) * ldp + col;
                    __nv_bfloat162 hh = *reinterpret_cast<const __nv_bfloat162*>(Xh + off);
                    __nv_bfloat162 hl = *reinterpret_cast<const __nv_bfloat162*>(Xl + off);
                    float h0 = __bfloat162float(hh.x) + __bfloat162float(hl.x);
                    float h1 = __bfloat162float(hh.y) + __bfloat162float(hl.y);
                    split_store(P1h, P1l, off,
                                cc[rr * 2] * (1.f - h0 * h0),
                                cc[rr * 2 + 1] * (1.f - h1 * h1));
                }
            } else {  // EPI_G
                *reinterpret_cast<float2*>(C + (size_t)r0 * ldc + col) =
                    make_float2(cc[0], cc[1]);
                *reinterpret_cast<float2*>(C + (size_t)(r0 + 8) * ldc + col) =
                    make_float2(cc[2], cc[3]);
            }
        }
    }
}

// ---------------- merged prep kernel ----------------
#define PB_W1   4096
#define PB_W2   (PB_W1 + 16384)
#define PB_W3   (PB_W2 + 4096)
#define PB_W1T  (PB_W3 + 1024)
#define PB_W2T  (PB_W1T + 4096)
#define PB_V3   (PB_W2T + 8)

__device__ __forceinline__ void seg_split(const float* __restrict__ W,
                                          __nv_bfloat16* __restrict__ hi,
                                          __nv_bfloat16* __restrict__ lo,
                                          int base, int tid) {
    int i = base * 256 + tid;
    float v = W[i];
    __nv_bfloat16 h = __float2bfloat16(v);
    hi[i] = h;
    lo[i] = __float2bfloat16(v - __bfloat162float(h));
}

__device__ __forceinline__ void seg_splitT(const float* __restrict__ in,
                                           __nv_bfloat16* __restrict__ hi,
                                           __nv_bfloat16* __restrict__ lo,
                                           int K, int Nn, int tileIdx, int tid) {
    __shared__ float t[32][33];
    int tilesX = K / 32;
    int k0 = (tileIdx % tilesX) * 32, n0 = (tileIdx / tilesX) * 32;
    int tx = tid & 31, ty = tid >> 5;
#pragma unroll
    for (int i = 0; i < 32; i += 8)
        t[ty + i][tx] = in[(size_t)(k0 + ty + i) * Nn + n0 + tx];
    __syncthreads();
#pragma unroll
    for (int i = 0; i < 32; i += 8) {
        float v = t[tx][ty + i];
        __nv_bfloat16 h = __float2bfloat16(v);
        size_t off = (size_t)(n0 + ty + i) * K + k0 + tx;
        hi[off] = h;
        lo[off] = __float2bfloat16(v - __bfloat162float(h));
    }
}

__global__ void __launch_bounds__(256) k_prep(const float* __restrict__ W1,
                                              const float* __restrict__ W2,
                                              const float* __restrict__ W3) {
    int b = blockIdx.x, tid = threadIdx.x;
    if (b < PB_W1) {
        seg_split(W1, g_W1h, g_W1l, b, tid);
    } else if (b < PB_W2) {
        seg_split(W2, g_W2h, g_W2l, b - PB_W1, tid);
    } else if (b < PB_W3) {
        seg_split(W3, g_W3h, g_W3l, b - PB_W2, tid);
    } else if (b < PB_W1T) {
        seg_splitT(W1, g_W1Th, g_W1Tl, HID, DIM, b - PB_W3, tid);
    } else if (b < PB_W2T) {
        seg_splitT(W2, g_W2Th, g_W2Tl, HID, HID, b - PB_W1T, tid);
    } else {
        int j = (b - PB_W2T) * 256 + tid;
        float s = 0.f;
#pragma unroll 8
        for (int i = 0; i < DIM; ++i) s += W3[(size_t)i * HID + j];
        g_v3[j] = s;
    }
}

__global__ void k_pack_z(const float* __restrict__ aug) {
    int b = blockIdx.x, t = threadIdx.x;
    float v = aug[(size_t)b * (DIM + 1) + t];
    __nv_bfloat16 h = __float2bfloat16(v);
    g_zh[(size_t)b * DIM + t] = h;
    g_zl[(size_t)b * DIM + t] = __float2bfloat16(v - __bfloat162float(h));
}

__global__ void k_trace(const float* __restrict__ eps, float* __restrict__ out) {
    int gw = (blockIdx.x * blockDim.x + threadIdx.x) >> 5;
    int lane = threadIdx.x & 31;
    const float* g  = g_g + (size_t)gw * DIM;
    const float* e0 = eps + (size_t)gw * DIM;
    const float* e1 = eps + ((size_t)BATCH + gw) * DIM;
    const float* e2 = eps + ((size_t)2 * BATCH + gw) * DIM;
    float s = 0.f;
    for (int d = lane * 4; d < DIM; d += 128) {
        float4 gv = *(const float4*)(g + d);
        float4 a  = *(const float4*)(e0 + d);
        float4 b  = *(const float4*)(e1 + d);
        float4 c  = *(const float4*)(e2 + d);
        s += gv.x * (a.x + b.x + c.x) + gv.y * (a.y + b.y + c.y)
           + gv.z * (a.z + b.z + c.z) + gv.w * (a.w + b.w + c.w);
    }
#pragma unroll
    for (int off = 16; off; off >>= 1) s += __shfl_xor_sync(0xFFFFFFFFu, s, off);
    if (lane == 0) out[(size_t)gw * (DIM + 1) + DIM] = s * (1.f / 3.f);
}

// ---------------- launch ----------------
extern "C" void kernel_launch(void* const* d_in, const int* in_sizes, int n_in,
                              void* d_out, int out_size) {
    const float* aug = (const float*)d_in[1];
    const float* eps = (const float*)d_in[2];
    const float* W1  = (const float*)d_in[3];
    const float* b1  = (const float*)d_in[4];
    const float* W2  = (const float*)d_in[5];
    const float* b2  = (const float*)d_in[6];
    const float* W3  = (const float*)d_in[7];
    const float* b3  = (const float*)d_in[8];
    float* out = (float*)d_out;

    __nv_bfloat16 *zh, *zl, *h1h, *h1l, *h2h, *h2l, *d2h, *d2l, *d1h, *d1l;
    cudaGetSymbolAddress((void**)&zh,  g_zh);  cudaGetSymbolAddress((void**)&zl,  g_zl);
    cudaGetSymbolAddress((void**)&h1h, g_h1h); cudaGetSymbolAddress((void**)&h1l, g_h1l);
    cudaGetSymbolAddress((void**)&h2h, g_h2h); cudaGetSymbolAddress((void**)&h2l, g_h2l);
    cudaGetSymbolAddress((void**)&d2h, g_d2h); cudaGetSymbolAddress((void**)&d2l, g_d2l);
    cudaGetSymbolAddress((void**)&d1h, g_d1h); cudaGetSymbolAddress((void**)&d1l, g_d1l);
    float *gg, *v3p;
    cudaGetSymbolAddress((void**)&gg,  g_g);
    cudaGetSymbolAddress((void**)&v3p, g_v3);
    __nv_bfloat16 *w1h, *w1l, *w2h, *w2l, *w3h, *w3l, *w2th, *w2tl, *w1th, *w1tl;
    cudaGetSymbolAddress((void**)&w1h,  g_W1h);  cudaGetSymbolAddress((void**)&w1l,  g_W1l);
    cudaGetSymbolAddress((void**)&w2h,  g_W2h);  cudaGetSymbolAddress((void**)&w2l,  g_W2l);
    cudaGetSymbolAddress((void**)&w3h,  g_W3h);  cudaGetSymbolAddress((void**)&w3l,  g_W3l);
    cudaGetSymbolAddress((void**)&w2th, g_W2Th); cudaGetSymbolAddress((void**)&w2tl, g_W2Tl);
    cudaGetSymbolAddress((void**)&w1th, g_W1Th); cudaGetSymbolAddress((void**)&w1tl, g_W1Tl);

    cudaFuncSetAttribute(mma_gemm<EPI_H1>,   cudaFuncAttributeMaxDynamicSharedMemorySize, SMEM_TOTAL);
    cudaFuncSetAttribute(mma_gemm<EPI_H2D2>, cudaFuncAttributeMaxDynamicSharedMemorySize, SMEM_TOTAL);
    cudaFuncSetAttribute(mma_gemm<EPI_OUT>,  cudaFuncAttributeMaxDynamicSharedMemorySize, SMEM_TOTAL);
    cudaFuncSetAttribute(mma_gemm<EPI_D1>,   cudaFuncAttributeMaxDynamicSharedMemorySize, SMEM_TOTAL);
    cudaFuncSetAttribute(mma_gemm<EPI_G>,    cudaFuncAttributeMaxDynamicSharedMemorySize, SMEM_TOTAL);

    // launch 0: all weight prep in one grid
    k_prep<<<PB_V3, 256>>>(W1, W2, W3);
    // launch 1: activation pack/split
    k_pack_z<<<BATCH, DIM>>>(aug);

    // launch 2 — G1: h1 = tanh(z @ W1^T + b1)   [K=512]
    mma_gemm<EPI_H1><<<dim3(HID / BN, BATCH / BM), THREADS, SMEM_TOTAL>>>(
        zh, zl, w1h, w1l, b1, nullptr, nullptr, 0,
        h1h, h1l, nullptr, nullptr, nullptr, nullptr, DIM, HID);
    // launch 3 — G2: h2 = tanh(h1 @ W2^T + b2); d2 = v3*(1-h2^2)
    mma_gemm<EPI_H2D2><<<dim3(HID / BN, BATCH / BM), THREADS, SMEM_TOTAL>>>(
        h1h, h1l, w2h, w2l, b2, v3p, nullptr, 0,
        h2h, h2l, d2h, d2l, nullptr, nullptr, HID, HID);
    // launch 4 — G3: dz_dt = h2 @ W3^T + b3 -> out[:, :512] (ldc=513)
    mma_gemm<EPI_OUT><<<dim3(DIM / BN, BATCH / BM), THREADS, SMEM_TOTAL>>>(
        h2h, h2l, w3h, w3l, b3, nullptr, out, DIM + 1,
        nullptr, nullptr, nullptr, nullptr, nullptr, nullptr, HID, 0);
    // launch 5 — G4: dh1 = d2 @ W2; d1 = dh1*(1-h1^2)   <-- ncu -s 5 captures this
    mma_gemm<EPI_D1><<<dim3(HID / BN, BATCH / BM), THREADS, SMEM_TOTAL>>>(
        d2h, d2l, w2th, w2tl, nullptr, nullptr, nullptr, 0,
        d1h, d1l, nullptr, nullptr, h1h, h1l, HID, HID);
    // launch 6 — G5: g = d1 @ W1
    mma_gemm<EPI_G><<<dim3(DIM / BN, BATCH / BM), THREADS, SMEM_TOTAL>>>(
        d1h, d1l, w1th, w1tl, nullptr, nullptr, gg, DIM,
        nullptr, nullptr, nullptr, nullptr, nullptr, nullptr, HID, 0);

    // launch 7 — trace column
    k_trace<<<BATCH / 8, 256>>>(eps, out);
}

// round 9
// speedup vs baseline: 1.2160x; 1.1157x over previous
#include <cuda_runtime.h>
#include <cuda_bf16.h>
#include <math.h>
#include <stdint.h>

#define BATCH 16384
#define DIM   512
#define HID   2048

#define BM 128
#define BN 128
#define BK 32
#define THREADS 128

// smem: 64B rows (32 bf16), XOR-swizzled 16B chunks -> conflict-free ldsm + STS
#define OA_H   0
#define OA_L   8192
#define OB_H   16384
#define OB_L   24576
#define STAGE  32768
#define NSTAGE 3
#define SMEM_TOTAL (NSTAGE * STAGE)   // 98304 -> 2 CTAs/SM

// ---------------- scratch (allocation-free) ----------------
__device__ __nv_bfloat16 g_zh[(size_t)BATCH * DIM],  g_zl[(size_t)BATCH * DIM];
__device__ __nv_bfloat16 g_h1h[(size_t)BATCH * HID], g_h1l[(size_t)BATCH * HID];
__device__ __nv_bfloat16 g_h2h[(size_t)BATCH * HID], g_h2l[(size_t)BATCH * HID];
__device__ __nv_bfloat16 g_d2h[(size_t)BATCH * HID], g_d2l[(size_t)BATCH * HID];
__device__ __nv_bfloat16 g_d1h[(size_t)BATCH * HID], g_d1l[(size_t)BATCH * HID];
__device__ float g_g[(size_t)BATCH * DIM];
__device__ float g_v3[HID];
__device__ __nv_bfloat16 g_W1h[HID * DIM],  g_W1l[HID * DIM];
__device__ __nv_bfloat16 g_W2h[HID * HID],  g_W2l[HID * HID];
__device__ __nv_bfloat16 g_W3h[DIM * HID],  g_W3l[DIM * HID];
__device__ __nv_bfloat16 g_W2Th[HID * HID], g_W2Tl[HID * HID];
__device__ __nv_bfloat16 g_W1Th[DIM * HID], g_W1Tl[DIM * HID];

enum { EPI_H1 = 0, EPI_H2D2 = 1, EPI_OUT = 2, EPI_D1 = 3, EPI_G = 4 };

// ---------------- helpers ----------------
__device__ __forceinline__ uint32_t s2u(const void* p) {
    uint32_t a;
    asm("{ .reg .u64 t; cvta.to.shared.u64 t, %1; cvt.u32.u64 %0, t; }" : "=r"(a) : "l"(p));
    return a;
}

// swizzled byte offset within a 128x32 bf16 tile: 64B rows, 16B chunk rotate by row>>1
__device__ __forceinline__ uint32_t swoff(int row, int seg) {
    return (uint32_t)(row * 64 + (((seg + (row >> 1)) & 3) << 4));
}

__device__ __forceinline__ void ldsm4(uint32_t* r, uint32_t addr) {
    asm volatile("ldmatrix.sync.aligned.m8n8.x4.shared.b16 {%0,%1,%2,%3}, [%4];"
                 : "=r"(r[0]), "=r"(r[1]), "=r"(r[2]), "=r"(r[3]) : "r"(addr));
}

__device__ __forceinline__ void mma16816(float* c, const uint32_t* a, const uint32_t* b) {
    asm volatile("mma.sync.aligned.m16n8k16.row.col.f32.bf16.bf16.f32 "
                 "{%0,%1,%2,%3}, {%4,%5,%6,%7}, {%8,%9}, {%0,%1,%2,%3};"
                 : "+f"(c[0]), "+f"(c[1]), "+f"(c[2]), "+f"(c[3])
                 : "r"(a[0]), "r"(a[1]), "r"(a[2]), "r"(a[3]), "r"(b[0]), "r"(b[1]));
}

__device__ __forceinline__ void cp16(uint32_t dst, const void* src) {
    asm volatile("cp.async.cg.shared.global [%0], [%1], 16;" :: "r"(dst), "l"(src) : "memory");
}

__device__ __forceinline__ float ftanh(float x) {
    float e = __expf(2.f * x);
    return 1.f - __fdividef(2.f, e + 1.f);
}

__device__ __forceinline__ void split_store(__nv_bfloat16* __restrict__ H,
                                            __nv_bfloat16* __restrict__ L,
                                            size_t off, float x, float y) {
    __nv_bfloat162 h = __floats2bfloat162_rn(x, y);
    __nv_bfloat162 l = __floats2bfloat162_rn(x - __bfloat162float(h.x),
                                             y - __bfloat162float(h.y));
    *reinterpret_cast<__nv_bfloat162*>(H + off) = h;
    *reinterpret_cast<__nv_bfloat162*>(L + off) = l;
}

// tile: 128 rows x 32 cols bf16 hi+lo via cp.async into swizzled smem (128 threads)
__device__ __forceinline__ void cpTile(uint32_t dstH, uint32_t dstL,
                                       const __nv_bfloat16* __restrict__ srcH,
                                       const __nv_bfloat16* __restrict__ srcL,
                                       int ld, int r0, int k0, int tid) {
#pragma unroll
    for (int i = 0; i < 4; ++i) {
        int idx = tid + i * 128;
        int row = idx >> 2, seg = idx & 3;
        size_t go = (size_t)(r0 + row) * ld + k0 + seg * 8;
        uint32_t so = swoff(row, seg);
        cp16(dstH + so, srcH + go);
        cp16(dstL + so, srcL + go);
    }
}

// ---------------- split-bf16 warp-MMA GEMM: 128x128 tile, 4 warps of 64x64 ----------------
template <int EPI>
__global__ void __launch_bounds__(THREADS, 2) mma_gemm(
    const __nv_bfloat16* __restrict__ Ah, const __nv_bfloat16* __restrict__ Al,
    const __nv_bfloat16* __restrict__ Bh, const __nv_bfloat16* __restrict__ Bl,
    const float* __restrict__ bias, const float* __restrict__ v3p,
    float* __restrict__ C, int ldc,
    __nv_bfloat16* __restrict__ P1h, __nv_bfloat16* __restrict__ P1l,
    __nv_bfloat16* __restrict__ P2h, __nv_bfloat16* __restrict__ P2l,
    const __nv_bfloat16* __restrict__ Xh, const __nv_bfloat16* __restrict__ Xl,
    int K, int ldp)
{
    extern __shared__ char smem[];
    const uint32_t sb = s2u(smem);
    const int tid = threadIdx.x, lane = tid & 31, wid = tid >> 5;
    const int wm = wid >> 1, wn = wid & 1;           // 2x2 warps, 64x64 each
    const int m0 = blockIdx.y * BM, n0 = blockIdx.x * BN;
    const int NC = K >> 5;

    float acc[4][8][4];
#pragma unroll
    for (int a = 0; a < 4; ++a)
#pragma unroll
        for (int b = 0; b < 8; ++b)
#pragma unroll
            for (int c = 0; c < 4; ++c) acc[a][b][c] = 0.f;

    // swizzled fragment base offsets (ks half toggles bit 5 via XOR)
    const int aRow = lane & 15;
    const int bRow = (lane & 7) + ((lane >> 4) << 3);
    uint32_t aBase[4], bBase[4];
#pragma unroll
    for (int mb = 0; mb < 4; ++mb)
        aBase[mb] = swoff(wm * 64 + mb * 16 + aRow, lane >> 4);
#pragma unroll
    for (int pr = 0; pr < 4; ++pr)
        bBase[pr] = swoff(wn * 64 + pr * 16 + bRow, (lane >> 3) & 1);

    // prologue: chunks 0,1 -> stages 0,1
#pragma unroll
    for (int c = 0; c < 2; ++c) {
        const uint32_t st = sb + c * STAGE;
        cpTile(st + OA_H, st + OA_L, Ah, Al, K, m0, c * BK, tid);
        cpTile(st + OB_H, st + OB_L, Bh, Bl, K, n0, c * BK, tid);
        asm volatile("cp.async.commit_group;" ::: "memory");
    }

    int sidx = 0;
    for (int c = 0; c < NC; ++c) {
        asm volatile("cp.async.wait_group 1;" ::: "memory");  // chunk c arrived
        __syncthreads();                                      // visibility + WAR (dist-2 write)
        if (c + 2 < NC) {
            int s2 = sidx + 2; if (s2 >= NSTAGE) s2 -= NSTAGE;
            const uint32_t nx = sb + s2 * STAGE;
            cpTile(nx + OA_H, nx + OA_L, Ah, Al, K, m0, (c + 2) * BK, tid);
            cpTile(nx + OB_H, nx + OB_L, Bh, Bl, K, n0, (c + 2) * BK, tid);
        }
        asm volatile("cp.async.commit_group;" ::: "memory");

        const uint32_t st = sb + sidx * STAGE;
#pragma unroll
        for (int ks = 0; ks < 2; ++ks) {
            const uint32_t kx = ks << 5;
            uint32_t bh[4][4], bl[4][4], ah[4][4], al[4][4];
#pragma unroll
            for (int pr = 0; pr < 4; ++pr) ldsm4(bh[pr], st + OB_H + (bBase[pr] ^ kx));
#pragma unroll
            for (int pr = 0; pr < 4; ++pr) ldsm4(bl[pr], st + OB_L + (bBase[pr] ^ kx));
#pragma unroll
            for (int mb = 0; mb < 4; ++mb) ldsm4(ah[mb], st + OA_H + (aBase[mb] ^ kx));
#pragma unroll
            for (int mb = 0; mb < 4; ++mb) ldsm4(al[mb], st + OA_L + (aBase[mb] ^ kx));
#pragma unroll
            for (int mb = 0; mb < 4; ++mb)
#pragma unroll
                for (int nb = 0; nb < 8; ++nb) {
                    const uint32_t* fh = &bh[nb >> 1][(nb & 1) * 2];
                    const uint32_t* fl = &bl[nb >> 1][(nb & 1) * 2];
                    mma16816(acc[mb][nb], ah[mb], fh);
                    mma16816(acc[mb][nb], ah[mb], fl);
                    mma16816(acc[mb][nb], al[mb], fh);
                }
        }
        if (++sidx == NSTAGE) sidx = 0;
    }

    // ---------------- epilogue ----------------
    const int g = lane >> 2, tg = lane & 3;
#pragma unroll
    for (int mb = 0; mb < 4; ++mb) {
#pragma unroll
        for (int nb = 0; nb < 8; ++nb) {
            float* cc = acc[mb][nb];
            const int r0 = m0 + wm * 64 + mb * 16 + g;
            const int col = n0 + wn * 64 + nb * 8 + tg * 2;
            if (EPI == EPI_H1) {
                float bx = __ldg(bias + col), by = __ldg(bias + col + 1);
                float t0 = ftanh(cc[0] + bx), t1 = ftanh(cc[1] + by);
                float t2 = ftanh(cc[2] + bx), t3 = ftanh(cc[3] + by);
                split_store(P1h, P1l, (size_t)r0 * ldp + col, t0, t1);
                split_store(P1h, P1l, (size_t)(r0 + 8) * ldp + col, t2, t3);
            } else if (EPI == EPI_H2D2) {
                float bx = __ldg(bias + col), by = __ldg(bias + col + 1);
                float vx = __ldg(v3p + col), vy = __ldg(v3p + col + 1);
                float t0 = ftanh(cc[0] + bx), t1 = ftanh(cc[1] + by);
                float t2 = ftanh(cc[2] + bx), t3 = ftanh(cc[3] + by);
                split_store(P1h, P1l, (size_t)r0 * ldp + col, t0, t1);
                split_store(P1h, P1l, (size_t)(r0 + 8) * ldp + col, t2, t3);
                split_store(P2h, P2l, (size_t)r0 * ldp + col,
                            vx * (1.f - t0 * t0), vy * (1.f - t1 * t1));
                split_store(P2h, P2l, (size_t)(r0 + 8) * ldp + col,
                            vx * (1.f - t2 * t2), vy * (1.f - t3 * t3));
            } else if (EPI == EPI_OUT) {
                float bx = __ldg(bias + col), by = __ldg(bias + col + 1);
                C[(size_t)r0 * ldc + col]     = cc[0] + bx;
                C[(size_t)r0 * ldc + col + 1] = cc[1] + by;
                C[(size_t)(r0 + 8) * ldc + col]     = cc[2] + bx;
                C[(size_t)(r0 + 8) * ldc + col + 1] = cc[3] + by;
            } else if (EPI == EPI_D1) {
#pragma unroll
                for (int rr = 0; rr < 2; ++rr) {
                    size_t off = (size_t)(r0 + rr * 8) * ldp + col;
                    __nv_bfloat162 hh = *reinterpret_cast<const __nv_bfloat162*>(Xh + off);
                    __nv_bfloat162 hl = *reinterpret_cast<const __nv_bfloat162*>(Xl + off);
                    float h0 = __bfloat162float(hh.x) + __bfloat162float(hl.x);
                    float h1 = __bfloat162float(hh.y) + __bfloat162float(hl.y);
                    split_store(P1h, P1l, off,
                                cc[rr * 2] * (1.f - h0 * h0),
                                cc[rr * 2 + 1] * (1.f - h1 * h1));
                }
            } else {  // EPI_G
                *reinterpret_cast<float2*>(C + (size_t)r0 * ldc + col) =
                    make_float2(cc[0], cc[1]);
                *reinterpret_cast<float2*>(C + (size_t)(r0 + 8) * ldc + col) =
                    make_float2(cc[2], cc[3]);
            }
        }
    }
}

// ---------------- merged prep kernel ----------------
#define PB_W1   4096
#define PB_W2   (PB_W1 + 16384)
#define PB_W3   (PB_W2 + 4096)
#define PB_W1T  (PB_W3 + 1024)
#define PB_W2T  (PB_W1T + 4096)
#define PB_V3   (PB_W2T + 8)

__device__ __forceinline__ void seg_split(const float* __restrict__ W,
                                          __nv_bfloat16* __restrict__ hi,
                                          __nv_bfloat16* __restrict__ lo,
                                          int base, int tid) {
    int i = base * 256 + tid;
    float v = W[i];
    __nv_bfloat16 h = __float2bfloat16(v);
    hi[i] = h;
    lo[i] = __float2bfloat16(v - __bfloat162float(h));
}

__device__ __forceinline__ void seg_splitT(const float* __restrict__ in,
                                           __nv_bfloat16* __restrict__ hi,
                                           __nv_bfloat16* __restrict__ lo,
                                           int K, int Nn, int tileIdx, int tid) {
    __shared__ float t[32][33];
    int tilesX = K / 32;
    int k0 = (tileIdx % tilesX) * 32, n0 = (tileIdx / tilesX) * 32;
    int tx = tid & 31, ty = tid >> 5;
#pragma unroll
    for (int i = 0; i < 32; i += 8)
        t[ty + i][tx] = in[(size_t)(k0 + ty + i) * Nn + n0 + tx];
    __syncthreads();
#pragma unroll
    for (int i = 0; i < 32; i += 8) {
        float v = t[tx][ty + i];
        __nv_bfloat16 h = __float2bfloat16(v);
        size_t off = (size_t)(n0 + ty + i) * K + k0 + tx;
        hi[off] = h;
        lo[off] = __float2bfloat16(v - __bfloat162float(h));
    }
}

__global__ void __launch_bounds__(256) k_prep(const float* __restrict__ W1,
                                              const float* __restrict__ W2,
                                              const float* __restrict__ W3) {
    int b = blockIdx.x, tid = threadIdx.x;
    if (b < PB_W1) {
        seg_split(W1, g_W1h, g_W1l, b, tid);
    } else if (b < PB_W2) {
        seg_split(W2, g_W2h, g_W2l, b - PB_W1, tid);
    } else if (b < PB_W3) {
        seg_split(W3, g_W3h, g_W3l, b - PB_W2, tid);
    } else if (b < PB_W1T) {
        seg_splitT(W1, g_W1Th, g_W1Tl, HID, DIM, b - PB_W3, tid);
    } else if (b < PB_W2T) {
        seg_splitT(W2, g_W2Th, g_W2Tl, HID, HID, b - PB_W1T, tid);
    } else {
        int j = (b - PB_W2T) * 256 + tid;
        float s = 0.f;
#pragma unroll 8
        for (int i = 0; i < DIM; ++i) s += W3[(size_t)i * HID + j];
        g_v3[j] = s;
    }
}

__global__ void k_pack_z(const float* __restrict__ aug) {
    int b = blockIdx.x, t = threadIdx.x;
    float v = aug[(size_t)b * (DIM + 1) + t];
    __nv_bfloat16 h = __float2bfloat16(v);
    g_zh[(size_t)b * DIM + t] = h;
    g_zl[(size_t)b * DIM + t] = __float2bfloat16(v - __bfloat162float(h));
}

__global__ void k_trace(const float* __restrict__ eps, float* __restrict__ out) {
    int gw = (blockIdx.x * blockDim.x + threadIdx.x) >> 5;
    int lane = threadIdx.x & 31;
    const float* g  = g_g + (size_t)gw * DIM;
    const float* e0 = eps + (size_t)gw * DIM;
    const float* e1 = eps + ((size_t)BATCH + gw) * DIM;
    const float* e2 = eps + ((size_t)2 * BATCH + gw) * DIM;
    float s = 0.f;
    for (int d = lane * 4; d < DIM; d += 128) {
        float4 gv = *(const float4*)(g + d);
        float4 a  = *(const float4*)(e0 + d);
        float4 b  = *(const float4*)(e1 + d);
        float4 c  = *(const float4*)(e2 + d);
        s += gv.x * (a.x + b.x + c.x) + gv.y * (a.y + b.y + c.y)
           + gv.z * (a.z + b.z + c.z) + gv.w * (a.w + b.w + c.w);
    }
#pragma unroll
    for (int off = 16; off; off >>= 1) s += __shfl_xor_sync(0xFFFFFFFFu, s, off);
    if (lane == 0) out[(size_t)gw * (DIM + 1) + DIM] = s * (1.f / 3.f);
}

// ---------------- launch ----------------
extern "C" void kernel_launch(void* const* d_in, const int* in_sizes, int n_in,
                              void* d_out, int out_size) {
    const float* aug = (const float*)d_in[1];
    const float* eps = (const float*)d_in[2];
    const float* W1  = (const float*)d_in[3];
    const float* b1  = (const float*)d_in[4];
    const float* W2  = (const float*)d_in[5];
    const float* b2  = (const float*)d_in[6];
    const float* W3  = (const float*)d_in[7];
    const float* b3  = (const float*)d_in[8];
    float* out = (float*)d_out;

    __nv_bfloat16 *zh, *zl, *h1h, *h1l, *h2h, *h2l, *d2h, *d2l, *d1h, *d1l;
    cudaGetSymbolAddress((void**)&zh,  g_zh);  cudaGetSymbolAddress((void**)&zl,  g_zl);
    cudaGetSymbolAddress((void**)&h1h, g_h1h); cudaGetSymbolAddress((void**)&h1l, g_h1l);
    cudaGetSymbolAddress((void**)&h2h, g_h2h); cudaGetSymbolAddress((void**)&h2l, g_h2l);
    cudaGetSymbolAddress((void**)&d2h, g_d2h); cudaGetSymbolAddress((void**)&d2l, g_d2l);
    cudaGetSymbolAddress((void**)&d1h, g_d1h); cudaGetSymbolAddress((void**)&d1l, g_d1l);
    float *gg, *v3p;
    cudaGetSymbolAddress((void**)&gg,  g_g);
    cudaGetSymbolAddress((void**)&v3p, g_v3);
    __nv_bfloat16 *w1h, *w1l, *w2h, *w2l, *w3h, *w3l, *w2th, *w2tl, *w1th, *w1tl;
    cudaGetSymbolAddress((void**)&w1h,  g_W1h);  cudaGetSymbolAddress((void**)&w1l,  g_W1l);
    cudaGetSymbolAddress((void**)&w2h,  g_W2h);  cudaGetSymbolAddress((void**)&w2l,  g_W2l);
    cudaGetSymbolAddress((void**)&w3h,  g_W3h);  cudaGetSymbolAddress((void**)&w3l,  g_W3l);
    cudaGetSymbolAddress((void**)&w2th, g_W2Th); cudaGetSymbolAddress((void**)&w2tl, g_W2Tl);
    cudaGetSymbolAddress((void**)&w1th, g_W1Th); cudaGetSymbolAddress((void**)&w1tl, g_W1Tl);

    cudaFuncSetAttribute(mma_gemm<EPI_H1>,   cudaFuncAttributeMaxDynamicSharedMemorySize, SMEM_TOTAL);
    cudaFuncSetAttribute(mma_gemm<EPI_H2D2>, cudaFuncAttributeMaxDynamicSharedMemorySize, SMEM_TOTAL);
    cudaFuncSetAttribute(mma_gemm<EPI_OUT>,  cudaFuncAttributeMaxDynamicSharedMemorySize, SMEM_TOTAL);
    cudaFuncSetAttribute(mma_gemm<EPI_D1>,   cudaFuncAttributeMaxDynamicSharedMemorySize, SMEM_TOTAL);
    cudaFuncSetAttribute(mma_gemm<EPI_G>,    cudaFuncAttributeMaxDynamicSharedMemorySize, SMEM_TOTAL);

    // launch 0: all weight prep in one grid
    k_prep<<<PB_V3, 256>>>(W1, W2, W3);
    // launch 1: activation pack/split
    k_pack_z<<<BATCH, DIM>>>(aug);

    // launch 2 — G1: h1 = tanh(z @ W1^T + b1)   [K=512]
    mma_gemm<EPI_H1><<<dim3(HID / BN, BATCH / BM), THREADS, SMEM_TOTAL>>>(
        zh, zl, w1h, w1l, b1, nullptr, nullptr, 0,
        h1h, h1l, nullptr, nullptr, nullptr, nullptr, DIM, HID);
    // launch 3 — G2: h2 = tanh(h1 @ W2^T + b2); d2 = v3*(1-h2^2)
    mma_gemm<EPI_H2D2><<<dim3(HID / BN, BATCH / BM), THREADS, SMEM_TOTAL>>>(
        h1h, h1l, w2h, w2l, b2, v3p, nullptr, 0,
        h2h, h2l, d2h, d2l, nullptr, nullptr, HID, HID);
    // launch 4 — G3: dz_dt = h2 @ W3^T + b3 -> out[:, :512] (ldc=513)
    mma_gemm<EPI_OUT><<<dim3(DIM / BN, BATCH / BM), THREADS, SMEM_TOTAL>>>(
        h2h, h2l, w3h, w3l, b3, nullptr, out, DIM + 1,
        nullptr, nullptr, nullptr, nullptr, nullptr, nullptr, HID, 0);
    // launch 5 — G4: dh1 = d2 @ W2; d1 = dh1*(1-h1^2)   <-- ncu -s 5 captures this
    mma_gemm<EPI_D1><<<dim3(HID / BN, BATCH / BM), THREADS, SMEM_TOTAL>>>(
        d2h, d2l, w2th, w2tl, nullptr, nullptr, nullptr, 0,
        d1h, d1l, nullptr, nullptr, h1h, h1l, HID, HID);
    // launch 6 — G5: g = d1 @ W1
    mma_gemm<EPI_G><<<dim3(DIM / BN, BATCH / BM), THREADS, SMEM_TOTAL>>>(
        d1h, d1l, w1th, w1tl, nullptr, nullptr, gg, DIM,
        nullptr, nullptr, nullptr, nullptr, nullptr, nullptr, HID, 0);

    // launch 7 — trace column
    k_trace<<<BATCH / 8, 256>>>(eps, out);
}

// round 10
// speedup vs baseline: 1.5587x; 1.2818x over previous
#include <cuda_runtime.h>
#include <cuda_fp16.h>
#include <math.h>
#include <stdint.h>

#define BATCH 16384
#define DIM   512
#define HID   2048

#define BM 128
#define BN 128
#define BK 32
#define THREADS 128

// smem: 64B rows (32 fp16), XOR-swizzled 16B chunks -> conflict-free ldsm + STS
#define OA_H   0
#define OA_L   8192
#define OB_H   16384
#define STAGE  24576
#define NSTAGE 3
#define SMEM_TOTAL (NSTAGE * STAGE)   // 73728 -> 2 CTAs/SM

// ---------------- scratch (allocation-free) ----------------
__device__ __half g_zh[(size_t)BATCH * DIM],  g_zl[(size_t)BATCH * DIM];
__device__ __half g_h1h[(size_t)BATCH * HID], g_h1l[(size_t)BATCH * HID];
__device__ __half g_h2h[(size_t)BATCH * HID], g_h2l[(size_t)BATCH * HID];
__device__ __half g_d2h[(size_t)BATCH * HID], g_d2l[(size_t)BATCH * HID];
__device__ __half g_d1h[(size_t)BATCH * HID], g_d1l[(size_t)BATCH * HID];
__device__ float g_g[(size_t)BATCH * DIM];
__device__ float g_v3[HID];
__device__ __half g_W1h[HID * DIM];
__device__ __half g_W2h[HID * HID];
__device__ __half g_W3h[DIM * HID];
__device__ __half g_W2Th[HID * HID];
__device__ __half g_W1Th[DIM * HID];

enum { EPI_H1 = 0, EPI_H2D2 = 1, EPI_OUT = 2, EPI_D1 = 3, EPI_G = 4 };

// ---------------- helpers ----------------
__device__ __forceinline__ uint32_t s2u(const void* p) {
    uint32_t a;
    asm("{ .reg .u64 t; cvta.to.shared.u64 t, %1; cvt.u32.u64 %0, t; }" : "=r"(a) : "l"(p));
    return a;
}

// swizzled byte offset within a 128x32 fp16 tile: 64B rows, 16B chunk rotate by row>>1
__device__ __forceinline__ uint32_t swoff(int row, int seg) {
    return (uint32_t)(row * 64 + (((seg + (row >> 1)) & 3) << 4));
}

__device__ __forceinline__ void ldsm4(uint32_t* r, uint32_t addr) {
    asm volatile("ldmatrix.sync.aligned.m8n8.x4.shared.b16 {%0,%1,%2,%3}, [%4];"
                 : "=r"(r[0]), "=r"(r[1]), "=r"(r[2]), "=r"(r[3]) : "r"(addr));
}

__device__ __forceinline__ void mma16816(float* c, const uint32_t* a, const uint32_t* b) {
    asm volatile("mma.sync.aligned.m16n8k16.row.col.f32.f16.f16.f32 "
                 "{%0,%1,%2,%3}, {%4,%5,%6,%7}, {%8,%9}, {%0,%1,%2,%3};"
                 : "+f"(c[0]), "+f"(c[1]), "+f"(c[2]), "+f"(c[3])
                 : "r"(a[0]), "r"(a[1]), "r"(a[2]), "r"(a[3]), "r"(b[0]), "r"(b[1]));
}

__device__ __forceinline__ void cp16(uint32_t dst, const void* src) {
    asm volatile("cp.async.cg.shared.global [%0], [%1], 16;" :: "r"(dst), "l"(src) : "memory");
}

__device__ __forceinline__ float ftanh(float x) {
    float e = __expf(2.f * x);
    return 1.f - __fdividef(2.f, e + 1.f);
}

__device__ __forceinline__ void split_store(__half* __restrict__ H,
                                            __half* __restrict__ L,
                                            size_t off, float x, float y) {
    __half hx = __float2half_rn(x), hy = __float2half_rn(y);
    __half lx = __float2half_rn(x - __half2float(hx));
    __half ly = __float2half_rn(y - __half2float(hy));
    *reinterpret_cast<__half2*>(H + off) = __halves2half2(hx, hy);
    *reinterpret_cast<__half2*>(L + off) = __halves2half2(lx, ly);
}

// one tile plane: 128 rows x 32 cols fp16 via cp.async into swizzled smem (128 threads)
__device__ __forceinline__ void cpPlane(uint32_t dst, const __half* __restrict__ src,
                                        int ld, int r0, int k0, int tid) {
#pragma unroll
    for (int i = 0; i < 4; ++i) {
        int idx = tid + i * 128;
        int row = idx >> 2, seg = idx & 3;
        cp16(dst + swoff(row, seg), src + (size_t)(r0 + row) * ld + k0 + seg * 8);
    }
}

// ---------------- fp16 2-term warp-MMA GEMM: 128x128 tile, 4 warps of 64x64 ----------------
// acc = (Ah + Al)[M,K] * (Bh[N,K])^T
template <int EPI>
__global__ void __launch_bounds__(THREADS, 2) mma_gemm(
    const __half* __restrict__ Ah, const __half* __restrict__ Al,
    const __half* __restrict__ Bh,
    const float* __restrict__ bias, const float* __restrict__ v3p,
    float* __restrict__ C, int ldc,
    __half* __restrict__ P1h, __half* __restrict__ P1l,
    __half* __restrict__ P2h, __half* __restrict__ P2l,
    const __half* __restrict__ Xh, const __half* __restrict__ Xl,
    int K, int ldp)
{
    extern __shared__ char smem[];
    const uint32_t sb = s2u(smem);
    const int tid = threadIdx.x, lane = tid & 31, wid = tid >> 5;
    const int wm = wid >> 1, wn = wid & 1;           // 2x2 warps, 64x64 each
    const int m0 = blockIdx.y * BM, n0 = blockIdx.x * BN;
    const int NC = K >> 5;

    float acc[4][8][4];
#pragma unroll
    for (int a = 0; a < 4; ++a)
#pragma unroll
        for (int b = 0; b < 8; ++b)
#pragma unroll
            for (int c = 0; c < 4; ++c) acc[a][b][c] = 0.f;

    // swizzled fragment base offsets (ks half toggles bit 5 via XOR)
    const int aRow = lane & 15;
    const int bRow = (lane & 7) + ((lane >> 4) << 3);
    uint32_t aBase[4], bBase[4];
#pragma unroll
    for (int mb = 0; mb < 4; ++mb)
        aBase[mb] = swoff(wm * 64 + mb * 16 + aRow, lane >> 4);
#pragma unroll
    for (int pr = 0; pr < 4; ++pr)
        bBase[pr] = swoff(wn * 64 + pr * 16 + bRow, (lane >> 3) & 1);

    // prologue: chunks 0,1 -> stages 0,1
#pragma unroll
    for (int c = 0; c < 2; ++c) {
        const uint32_t st = sb + c * STAGE;
        cpPlane(st + OA_H, Ah, K, m0, c * BK, tid);
        cpPlane(st + OA_L, Al, K, m0, c * BK, tid);
        cpPlane(st + OB_H, Bh, K, n0, c * BK, tid);
        asm volatile("cp.async.commit_group;" ::: "memory");
    }

    int sidx = 0;
    for (int c = 0; c < NC; ++c) {
        asm volatile("cp.async.wait_group 1;" ::: "memory");  // chunk c arrived
        __syncthreads();                                      // visibility + WAR (dist-2 write)
        if (c + 2 < NC) {
            int s2 = sidx + 2; if (s2 >= NSTAGE) s2 -= NSTAGE;
            const uint32_t nx = sb + s2 * STAGE;
            cpPlane(nx + OA_H, Ah, K, m0, (c + 2) * BK, tid);
            cpPlane(nx + OA_L, Al, K, m0, (c + 2) * BK, tid);
            cpPlane(nx + OB_H, Bh, K, n0, (c + 2) * BK, tid);
        }
        asm volatile("cp.async.commit_group;" ::: "memory");

        const uint32_t st = sb + sidx * STAGE;
#pragma unroll
        for (int ks = 0; ks < 2; ++ks) {
            const uint32_t kx = ks << 5;
            uint32_t bh[4][4], ah[4][4], al[4][4];
#pragma unroll
            for (int pr = 0; pr < 4; ++pr) ldsm4(bh[pr], st + OB_H + (bBase[pr] ^ kx));
#pragma unroll
            for (int mb = 0; mb < 4; ++mb) ldsm4(ah[mb], st + OA_H + (aBase[mb] ^ kx));
#pragma unroll
            for (int mb = 0; mb < 4; ++mb) ldsm4(al[mb], st + OA_L + (aBase[mb] ^ kx));
#pragma unroll
            for (int mb = 0; mb < 4; ++mb)
#pragma unroll
                for (int nb = 0; nb < 8; ++nb) {
                    const uint32_t* fh = &bh[nb >> 1][(nb & 1) * 2];
                    mma16816(acc[mb][nb], ah[mb], fh);
                    mma16816(acc[mb][nb], al[mb], fh);
                }
        }
        if (++sidx == NSTAGE) sidx = 0;
    }

    // ---------------- epilogue ----------------
    const int g = lane >> 2, tg = lane & 3;
#pragma unroll
    for (int mb = 0; mb < 4; ++mb) {
#pragma unroll
        for (int nb = 0; nb < 8; ++nb) {
            float* cc = acc[mb][nb];
            const int r0 = m0 + wm * 64 + mb * 16 + g;
            const int col = n0 + wn * 64 + nb * 8 + tg * 2;
            if (EPI == EPI_H1) {
                float bx = __ldg(bias + col), by = __ldg(bias + col + 1);
                float t0 = ftanh(cc[0] + bx), t1 = ftanh(cc[1] + by);
                float t2 = ftanh(cc[2] + bx), t3 = ftanh(cc[3] + by);
                split_store(P1h, P1l, (size_t)r0 * ldp + col, t0, t1);
                split_store(P1h, P1l, (size_t)(r0 + 8) * ldp + col, t2, t3);
            } else if (EPI == EPI_H2D2) {
                float bx = __ldg(bias + col), by = __ldg(bias + col + 1);
                float vx = __ldg(v3p + col), vy = __ldg(v3p + col + 1);
                float t0 = ftanh(cc[0] + bx), t1 = ftanh(cc[1] + by);
                float t2 = ftanh(cc[2] + bx), t3 = ftanh(cc[3] + by);
                split_store(P1h, P1l, (size_t)r0 * ldp + col, t0, t1);
                split_store(P1h, P1l, (size_t)(r0 + 8) * ldp + col, t2, t3);
                split_store(P2h, P2l, (size_t)r0 * ldp + col,
                            vx * (1.f - t0 * t0), vy * (1.f - t1 * t1));
                split_store(P2h, P2l, (size_t)(r0 + 8) * ldp + col,
                            vx * (1.f - t2 * t2), vy * (1.f - t3 * t3));
            } else if (EPI == EPI_OUT) {
                float bx = __ldg(bias + col), by = __ldg(bias + col + 1);
                C[(size_t)r0 * ldc + col]     = cc[0] + bx;
                C[(size_t)r0 * ldc + col + 1] = cc[1] + by;
                C[(size_t)(r0 + 8) * ldc + col]     = cc[2] + bx;
                C[(size_t)(r0 + 8) * ldc + col + 1] = cc[3] + by;
            } else if (EPI == EPI_D1) {
#pragma unroll
                for (int rr = 0; rr < 2; ++rr) {
                    size_t off = (size_t)(r0 + rr * 8) * ldp + col;
                    __half2 hh = *reinterpret_cast<const __half2*>(Xh + off);
                    __half2 hl = *reinterpret_cast<const __half2*>(Xl + off);
                    float h0 = __half2float(hh.x) + __half2float(hl.x);
                    float h1 = __half2float(hh.y) + __half2float(hl.y);
                    split_store(P1h, P1l, off,
                                cc[rr * 2] * (1.f - h0 * h0),
                                cc[rr * 2 + 1] * (1.f - h1 * h1));
                }
            } else {  // EPI_G
                *reinterpret_cast<float2*>(C + (size_t)r0 * ldc + col) =
                    make_float2(cc[0], cc[1]);
                *reinterpret_cast<float2*>(C + (size_t)(r0 + 8) * ldc + col) =
                    make_float2(cc[2], cc[3]);
            }
        }
    }
}

// ---------------- merged prep kernel ----------------
#define PB_W1   4096
#define PB_W2   (PB_W1 + 16384)
#define PB_W3   (PB_W2 + 4096)
#define PB_W1T  (PB_W3 + 1024)
#define PB_W2T  (PB_W1T + 4096)
#define PB_V3   (PB_W2T + 8)

__device__ __forceinline__ void seg_split(const float* __restrict__ W,
                                          __half* __restrict__ hi,
                                          int base, int tid) {
    int i = base * 256 + tid;
    hi[i] = __float2half_rn(W[i]);
}

__device__ __forceinline__ void seg_splitT(const float* __restrict__ in,
                                           __half* __restrict__ hi,
                                           int K, int Nn, int tileIdx, int tid) {
    __shared__ float t[32][33];
    int tilesX = K / 32;
    int k0 = (tileIdx % tilesX) * 32, n0 = (tileIdx / tilesX) * 32;
    int tx = tid & 31, ty = tid >> 5;
#pragma unroll
    for (int i = 0; i < 32; i += 8)
        t[ty + i][tx] = in[(size_t)(k0 + ty + i) * Nn + n0 + tx];
    __syncthreads();
#pragma unroll
    for (int i = 0; i < 32; i += 8)
        hi[(size_t)(n0 + ty + i) * K + k0 + tx] = __float2half_rn(t[tx][ty + i]);
}

__global__ void __launch_bounds__(256) k_prep(const float* __restrict__ W1,
                                              const float* __restrict__ W2,
                                              const float* __restrict__ W3) {
    int b = blockIdx.x, tid = threadIdx.x;
    if (b < PB_W1) {
        seg_split(W1, g_W1h, b, tid);
    } else if (b < PB_W2) {
        seg_split(W2, g_W2h, b - PB_W1, tid);
    } else if (b < PB_W3) {
        seg_split(W3, g_W3h, b - PB_W2, tid);
    } else if (b < PB_W1T) {
        seg_splitT(W1, g_W1Th, HID, DIM, b - PB_W3, tid);
    } else if (b < PB_W2T) {
        seg_splitT(W2, g_W2Th, HID, HID, b - PB_W1T, tid);
    } else {
        int j = (b - PB_W2T) * 256 + tid;
        float s = 0.f;
#pragma unroll 8
        for (int i = 0; i < DIM; ++i) s += W3[(size_t)i * HID + j];
        g_v3[j] = s;
    }
}

__global__ void k_pack_z(const float* __restrict__ aug) {
    int b = blockIdx.x, t = threadIdx.x;
    float v = aug[(size_t)b * (DIM + 1) + t];
    __half h = __float2half_rn(v);
    g_zh[(size_t)b * DIM + t] = h;
    g_zl[(size_t)b * DIM + t] = __float2half_rn(v - __half2float(h));
}

__global__ void k_trace(const float* __restrict__ eps, float* __restrict__ out) {
    int gw = (blockIdx.x * blockDim.x + threadIdx.x) >> 5;
    int lane = threadIdx.x & 31;
    const float* g  = g_g + (size_t)gw * DIM;
    const float* e0 = eps + (size_t)gw * DIM;
    const float* e1 = eps + ((size_t)BATCH + gw) * DIM;
    const float* e2 = eps + ((size_t)2 * BATCH + gw) * DIM;
    float s = 0.f;
    for (int d = lane * 4; d < DIM; d += 128) {
        float4 gv = *(const float4*)(g + d);
        float4 a  = *(const float4*)(e0 + d);
        float4 b  = *(const float4*)(e1 + d);
        float4 c  = *(const float4*)(e2 + d);
        s += gv.x * (a.x + b.x + c.x) + gv.y * (a.y + b.y + c.y)
           + gv.z * (a.z + b.z + c.z) + gv.w * (a.w + b.w + c.w);
    }
#pragma unroll
    for (int off = 16; off; off >>= 1) s += __shfl_xor_sync(0xFFFFFFFFu, s, off);
    if (lane == 0) out[(size_t)gw * (DIM + 1) + DIM] = s * (1.f / 3.f);
}

// ---------------- launch ----------------
extern "C" void kernel_launch(void* const* d_in, const int* in_sizes, int n_in,
                              void* d_out, int out_size) {
    const float* aug = (const float*)d_in[1];
    const float* eps = (const float*)d_in[2];
    const float* W1  = (const float*)d_in[3];
    const float* b1  = (const float*)d_in[4];
    const float* W2  = (const float*)d_in[5];
    const float* b2  = (const float*)d_in[6];
    const float* W3  = (const float*)d_in[7];
    const float* b3  = (const float*)d_in[8];
    float* out = (float*)d_out;

    __half *zh, *zl, *h1h, *h1l, *h2h, *h2l, *d2h, *d2l, *d1h, *d1l;
    cudaGetSymbolAddress((void**)&zh,  g_zh);  cudaGetSymbolAddress((void**)&zl,  g_zl);
    cudaGetSymbolAddress((void**)&h1h, g_h1h); cudaGetSymbolAddress((void**)&h1l, g_h1l);
    cudaGetSymbolAddress((void**)&h2h, g_h2h); cudaGetSymbolAddress((void**)&h2l, g_h2l);
    cudaGetSymbolAddress((void**)&d2h, g_d2h); cudaGetSymbolAddress((void**)&d2l, g_d2l);
    cudaGetSymbolAddress((void**)&d1h, g_d1h); cudaGetSymbolAddress((void**)&d1l, g_d1l);
    float *gg, *v3p;
    cudaGetSymbolAddress((void**)&gg,  g_g);
    cudaGetSymbolAddress((void**)&v3p, g_v3);
    __half *w1h, *w2h, *w3h, *w2th, *w1th;
    cudaGetSymbolAddress((void**)&w1h,  g_W1h);
    cudaGetSymbolAddress((void**)&w2h,  g_W2h);
    cudaGetSymbolAddress((void**)&w3h,  g_W3h);
    cudaGetSymbolAddress((void**)&w2th, g_W2Th);
    cudaGetSymbolAddress((void**)&w1th, g_W1Th);

    cudaFuncSetAttribute(mma_gemm<EPI_H1>,   cudaFuncAttributeMaxDynamicSharedMemorySize, SMEM_TOTAL);
    cudaFuncSetAttribute(mma_gemm<EPI_H2D2>, cudaFuncAttributeMaxDynamicSharedMemorySize, SMEM_TOTAL);
    cudaFuncSetAttribute(mma_gemm<EPI_OUT>,  cudaFuncAttributeMaxDynamicSharedMemorySize, SMEM_TOTAL);
    cudaFuncSetAttribute(mma_gemm<EPI_D1>,   cudaFuncAttributeMaxDynamicSharedMemorySize, SMEM_TOTAL);
    cudaFuncSetAttribute(mma_gemm<EPI_G>,    cudaFuncAttributeMaxDynamicSharedMemorySize, SMEM_TOTAL);

    // launch 0: all weight prep in one grid
    k_prep<<<PB_V3, 256>>>(W1, W2, W3);
    // launch 1: activation pack/split
    k_pack_z<<<BATCH, DIM>>>(aug);

    // launch 2 — G1: h1 = tanh(z @ W1^T + b1)   [K=512]
    mma_gemm<EPI_H1><<<dim3(HID / BN, BATCH / BM), THREADS, SMEM_TOTAL>>>(
        zh, zl, w1h, b1, nullptr, nullptr, 0,
        h1h, h1l, nullptr, nullptr, nullptr, nullptr, DIM, HID);
    // launch 3 — G2: h2 = tanh(h1 @ W2^T + b2); d2 = v3*(1-h2^2)
    mma_gemm<EPI_H2D2><<<dim3(HID / BN, BATCH / BM), THREADS, SMEM_TOTAL>>>(
        h1h, h1l, w2h, b2, v3p, nullptr, 0,
        h2h, h2l, d2h, d2l, nullptr, nullptr, HID, HID);
    // launch 4 — G3: dz_dt = h2 @ W3^T + b3 -> out[:, :512] (ldc=513)
    mma_gemm<EPI_OUT><<<dim3(DIM / BN, BATCH / BM), THREADS, SMEM_TOTAL>>>(
        h2h, h2l, w3h, b3, nullptr, out, DIM + 1,
        nullptr, nullptr, nullptr, nullptr, nullptr, nullptr, HID, 0);
    // launch 5 — G4: dh1 = d2 @ W2; d1 = dh1*(1-h1^2)   <-- ncu -s 5 captures this
    mma_gemm<EPI_D1><<<dim3(HID / BN, BATCH / BM), THREADS, SMEM_TOTAL>>>(
        d2h, d2l, w2th, nullptr, nullptr, nullptr, 0,
        d1h, d1l, nullptr, nullptr, h1h, h1l, HID, HID);
    // launch 6 — G5: g = d1 @ W1
    mma_gemm<EPI_G><<<dim3(DIM / BN, BATCH / BM), THREADS, SMEM_TOTAL>>>(
        d1h, d1l, w1th, nullptr, nullptr, gg, DIM,
        nullptr, nullptr, nullptr, nullptr, nullptr, nullptr, HID, 0);

    // launch 7 — trace column
    k_trace<<<BATCH / 8, 256>>>(eps, out);
}

// round 11
// speedup vs baseline: 3.1970x; 2.0511x over previous
#include <cuda_runtime.h>
#include <cuda_fp16.h>
#include <math.h>
#include <stdint.h>

#define BATCH 16384
#define DIM   512
#define HID   2048

#define BM 128
#define BN 128
#define BK 32
#define THREADS 128

// smem: 64B rows (32 fp16), XOR-swizzled 16B chunks -> conflict-free ldsm + STS
#define OA_H   0
#define OB_H   8192
#define STAGE  16384
#define NSTAGE 4
#define SMEM_TOTAL (NSTAGE * STAGE)   // 65536 -> 2 CTAs/SM easily

// ---------------- scratch (allocation-free) ----------------
__device__ __half g_zh[(size_t)BATCH * DIM];
__device__ __half g_h1h[(size_t)BATCH * HID];
__device__ __half g_h2h[(size_t)BATCH * HID];
__device__ __half g_d2h[(size_t)BATCH * HID];
__device__ __half g_d1h[(size_t)BATCH * HID];
__device__ float g_g[(size_t)BATCH * DIM];
__device__ float g_v3[HID];
__device__ __half g_W1h[HID * DIM];
__device__ __half g_W2h[HID * HID];
__device__ __half g_W3h[DIM * HID];
__device__ __half g_W2Th[HID * HID];
__device__ __half g_W1Th[DIM * HID];

enum { EPI_H1 = 0, EPI_H2D2 = 1, EPI_OUT = 2, EPI_D1 = 3, EPI_G = 4 };

// ---------------- helpers ----------------
__device__ __forceinline__ uint32_t s2u(const void* p) {
    uint32_t a;
    asm("{ .reg .u64 t; cvta.to.shared.u64 t, %1; cvt.u32.u64 %0, t; }" : "=r"(a) : "l"(p));
    return a;
}

// swizzled byte offset within a 128x32 fp16 tile: 64B rows, 16B chunk rotate by row>>1
__device__ __forceinline__ uint32_t swoff(int row, int seg) {
    return (uint32_t)(row * 64 + (((seg + (row >> 1)) & 3) << 4));
}

__device__ __forceinline__ void ldsm4(uint32_t* r, uint32_t addr) {
    asm volatile("ldmatrix.sync.aligned.m8n8.x4.shared.b16 {%0,%1,%2,%3}, [%4];"
                 : "=r"(r[0]), "=r"(r[1]), "=r"(r[2]), "=r"(r[3]) : "r"(addr));
}

__device__ __forceinline__ void mma16816(float* c, const uint32_t* a, const uint32_t* b) {
    asm volatile("mma.sync.aligned.m16n8k16.row.col.f32.f16.f16.f32 "
                 "{%0,%1,%2,%3}, {%4,%5,%6,%7}, {%8,%9}, {%0,%1,%2,%3};"
                 : "+f"(c[0]), "+f"(c[1]), "+f"(c[2]), "+f"(c[3])
                 : "r"(a[0]), "r"(a[1]), "r"(a[2]), "r"(a[3]), "r"(b[0]), "r"(b[1]));
}

__device__ __forceinline__ void cp16(uint32_t dst, const void* src) {
    asm volatile("cp.async.cg.shared.global [%0], [%1], 16;" :: "r"(dst), "l"(src) : "memory");
}

__device__ __forceinline__ float ftanh(float x) {
    float e = __expf(2.f * x);
    return 1.f - __fdividef(2.f, e + 1.f);
}

// one tile plane: 128 rows x 32 cols fp16 via cp.async into swizzled smem (128 threads)
__device__ __forceinline__ void cpPlane(uint32_t dst, const __half* __restrict__ src,
                                        int ld, int r0, int k0, int tid) {
#pragma unroll
    for (int i = 0; i < 4; ++i) {
        int idx = tid + i * 128;
        int row = idx >> 2, seg = idx & 3;
        cp16(dst + swoff(row, seg), src + (size_t)(r0 + row) * ld + k0 + seg * 8);
    }
}

// ---------------- fp16 warp-MMA GEMM: 128x128 tile, 4 warps of 64x64, 4-stage ----------------
// acc = Ah[M,K] * (Bh[N,K])^T
template <int EPI>
__global__ void __launch_bounds__(THREADS, 2) mma_gemm(
    const __half* __restrict__ Ah, const __half* __restrict__ Bh,
    const float* __restrict__ bias, const float* __restrict__ v3p,
    float* __restrict__ C, int ldc,
    __half* __restrict__ P1, __half* __restrict__ P2,
    const __half* __restrict__ Xh,
    int K, int ldp)
{
    extern __shared__ char smem[];
    const uint32_t sb = s2u(smem);
    const int tid = threadIdx.x, lane = tid & 31, wid = tid >> 5;
    const int wm = wid >> 1, wn = wid & 1;           // 2x2 warps, 64x64 each
    const int m0 = blockIdx.y * BM, n0 = blockIdx.x * BN;
    const int NC = K >> 5;

    float acc[4][8][4];
#pragma unroll
    for (int a = 0; a < 4; ++a)
#pragma unroll
        for (int b = 0; b < 8; ++b)
#pragma unroll
            for (int c = 0; c < 4; ++c) acc[a][b][c] = 0.f;

    // swizzled fragment base offsets (ks half toggles bit 5 via XOR)
    const int aRow = lane & 15;
    const int bRow = (lane & 7) + ((lane >> 4) << 3);
    uint32_t aBase[4], bBase[4];
#pragma unroll
    for (int mb = 0; mb < 4; ++mb)
        aBase[mb] = swoff(wm * 64 + mb * 16 + aRow, lane >> 4);
#pragma unroll
    for (int pr = 0; pr < 4; ++pr)
        bBase[pr] = swoff(wn * 64 + pr * 16 + bRow, (lane >> 3) & 1);

    // prologue: chunks 0..2 -> stages 0..2
#pragma unroll
    for (int c = 0; c < 3; ++c) {
        const uint32_t st = sb + c * STAGE;
        if (c < NC) {
            cpPlane(st + OA_H, Ah, K, m0, c * BK, tid);
            cpPlane(st + OB_H, Bh, K, n0, c * BK, tid);
        }
        asm volatile("cp.async.commit_group;" ::: "memory");
    }

    int sidx = 0;
    for (int c = 0; c < NC; ++c) {
        asm volatile("cp.async.wait_group 2;" ::: "memory");  // chunk c arrived
        __syncthreads();                                      // visibility + WAR (dist-3 write)
        if (c + 3 < NC) {
            int s2 = sidx + 3; if (s2 >= NSTAGE) s2 -= NSTAGE;
            const uint32_t nx = sb + s2 * STAGE;
            cpPlane(nx + OA_H, Ah, K, m0, (c + 3) * BK, tid);
            cpPlane(nx + OB_H, Bh, K, n0, (c + 3) * BK, tid);
        }
        asm volatile("cp.async.commit_group;" ::: "memory");

        const uint32_t st = sb + sidx * STAGE;
#pragma unroll
        for (int ks = 0; ks < 2; ++ks) {
            const uint32_t kx = ks << 5;
            uint32_t bh[4][4], ah[4][4];
#pragma unroll
            for (int pr = 0; pr < 4; ++pr) ldsm4(bh[pr], st + OB_H + (bBase[pr] ^ kx));
#pragma unroll
            for (int mb = 0; mb < 4; ++mb) ldsm4(ah[mb], st + OA_H + (aBase[mb] ^ kx));
#pragma unroll
            for (int mb = 0; mb < 4; ++mb)
#pragma unroll
                for (int nb = 0; nb < 8; ++nb) {
                    const uint32_t* fh = &bh[nb >> 1][(nb & 1) * 2];
                    mma16816(acc[mb][nb], ah[mb], fh);
                }
        }
        if (++sidx == NSTAGE) sidx = 0;
    }

    // ---------------- epilogue ----------------
    const int g = lane >> 2, tg = lane & 3;
#pragma unroll
    for (int mb = 0; mb < 4; ++mb) {
#pragma unroll
        for (int nb = 0; nb < 8; ++nb) {
            float* cc = acc[mb][nb];
            const int r0 = m0 + wm * 64 + mb * 16 + g;
            const int col = n0 + wn * 64 + nb * 8 + tg * 2;
            if (EPI == EPI_H1) {
                float bx = __ldg(bias + col), by = __ldg(bias + col + 1);
                float t0 = ftanh(cc[0] + bx), t1 = ftanh(cc[1] + by);
                float t2 = ftanh(cc[2] + bx), t3 = ftanh(cc[3] + by);
                *reinterpret_cast<__half2*>(P1 + (size_t)r0 * ldp + col) =
                    __halves2half2(__float2half_rn(t0), __float2half_rn(t1));
                *reinterpret_cast<__half2*>(P1 + (size_t)(r0 + 8) * ldp + col) =
                    __halves2half2(__float2half_rn(t2), __float2half_rn(t3));
            } else if (EPI == EPI_H2D2) {
                float bx = __ldg(bias + col), by = __ldg(bias + col + 1);
                float vx = __ldg(v3p + col), vy = __ldg(v3p + col + 1);
                float t0 = ftanh(cc[0] + bx), t1 = ftanh(cc[1] + by);
                float t2 = ftanh(cc[2] + bx), t3 = ftanh(cc[3] + by);
                *reinterpret_cast<__half2*>(P1 + (size_t)r0 * ldp + col) =
                    __halves2half2(__float2half_rn(t0), __float2half_rn(t1));
                *reinterpret_cast<__half2*>(P1 + (size_t)(r0 + 8) * ldp + col) =
                    __halves2half2(__float2half_rn(t2), __float2half_rn(t3));
                *reinterpret_cast<__half2*>(P2 + (size_t)r0 * ldp + col) =
                    __halves2half2(__float2half_rn(vx * (1.f - t0 * t0)),
                                   __float2half_rn(vy * (1.f - t1 * t1)));
                *reinterpret_cast<__half2*>(P2 + (size_t)(r0 + 8) * ldp + col) =
                    __halves2half2(__float2half_rn(vx * (1.f - t2 * t2)),
                                   __float2half_rn(vy * (1.f - t3 * t3)));
            } else if (EPI == EPI_OUT) {
                float bx = __ldg(bias + col), by = __ldg(bias + col + 1);
                C[(size_t)r0 * ldc + col]     = cc[0] + bx;
                C[(size_t)r0 * ldc + col + 1] = cc[1] + by;
                C[(size_t)(r0 + 8) * ldc + col]     = cc[2] + bx;
                C[(size_t)(r0 + 8) * ldc + col + 1] = cc[3] + by;
            } else if (EPI == EPI_D1) {
#pragma unroll
                for (int rr = 0; rr < 2; ++rr) {
                    size_t off = (size_t)(r0 + rr * 8) * ldp + col;
                    __half2 hh = *reinterpret_cast<const __half2*>(Xh + off);
                    float h0 = __half2float(hh.x), h1 = __half2float(hh.y);
                    *reinterpret_cast<__half2*>(P1 + off) = __halves2half2(
                        __float2half_rn(cc[rr * 2] * (1.f - h0 * h0)),
                        __float2half_rn(cc[rr * 2 + 1] * (1.f - h1 * h1)));
                }
            } else {  // EPI_G
                *reinterpret_cast<float2*>(C + (size_t)r0 * ldc + col) =
                    make_float2(cc[0], cc[1]);
                *reinterpret_cast<float2*>(C + (size_t)(r0 + 8) * ldc + col) =
                    make_float2(cc[2], cc[3]);
            }
        }
    }
}

// ---------------- merged prep kernel ----------------
#define PB_W1   4096
#define PB_W2   (PB_W1 + 16384)
#define PB_W3   (PB_W2 + 4096)
#define PB_W1T  (PB_W3 + 1024)
#define PB_W2T  (PB_W1T + 4096)
#define PB_V3   (PB_W2T + 8)

__device__ __forceinline__ void seg_split(const float* __restrict__ W,
                                          __half* __restrict__ hi,
                                          int base, int tid) {
    int i = base * 256 + tid;
    hi[i] = __float2half_rn(W[i]);
}

__device__ __forceinline__ void seg_splitT(const float* __restrict__ in,
                                           __half* __restrict__ hi,
                                           int K, int Nn, int tileIdx, int tid) {
    __shared__ float t[32][33];
    int tilesX = K / 32;
    int k0 = (tileIdx % tilesX) * 32, n0 = (tileIdx / tilesX) * 32;
    int tx = tid & 31, ty = tid >> 5;
#pragma unroll
    for (int i = 0; i < 32; i += 8)
        t[ty + i][tx] = in[(size_t)(k0 + ty + i) * Nn + n0 + tx];
    __syncthreads();
#pragma unroll
    for (int i = 0; i < 32; i += 8)
        hi[(size_t)(n0 + ty + i) * K + k0 + tx] = __float2half_rn(t[tx][ty + i]);
}

__global__ void __launch_bounds__(256) k_prep(const float* __restrict__ W1,
                                              const float* __restrict__ W2,
                                              const float* __restrict__ W3) {
    int b = blockIdx.x, tid = threadIdx.x;
    if (b < PB_W1) {
        seg_split(W1, g_W1h, b, tid);
    } else if (b < PB_W2) {
        seg_split(W2, g_W2h, b - PB_W1, tid);
    } else if (b < PB_W3) {
        seg_split(W3, g_W3h, b - PB_W2, tid);
    } else if (b < PB_W1T) {
        seg_splitT(W1, g_W1Th, HID, DIM, b - PB_W3, tid);
    } else if (b < PB_W2T) {
        seg_splitT(W2, g_W2Th, HID, HID, b - PB_W1T, tid);
    } else {
        int j = (b - PB_W2T) * 256 + tid;
        float s = 0.f;
#pragma unroll 8
        for (int i = 0; i < DIM; ++i) s += W3[(size_t)i * HID + j];
        g_v3[j] = s;
    }
}

__global__ void k_pack_z(const float* __restrict__ aug) {
    int b = blockIdx.x, t = threadIdx.x;
    g_zh[(size_t)b * DIM + t] = __float2half_rn(aug[(size_t)b * (DIM + 1) + t]);
}

__global__ void k_trace(const float* __restrict__ eps, float* __restrict__ out) {
    int gw = (blockIdx.x * blockDim.x + threadIdx.x) >> 5;
    int lane = threadIdx.x & 31;
    const float* g  = g_g + (size_t)gw * DIM;
    const float* e0 = eps + (size_t)gw * DIM;
    const float* e1 = eps + ((size_t)BATCH + gw) * DIM;
    const float* e2 = eps + ((size_t)2 * BATCH + gw) * DIM;
    float s = 0.f;
    for (int d = lane * 4; d < DIM; d += 128) {
        float4 gv = *(const float4*)(g + d);
        float4 a  = *(const float4*)(e0 + d);
        float4 b  = *(const float4*)(e1 + d);
        float4 c  = *(const float4*)(e2 + d);
        s += gv.x * (a.x + b.x + c.x) + gv.y * (a.y + b.y + c.y)
           + gv.z * (a.z + b.z + c.z) + gv.w * (a.w + b.w + c.w);
    }
#pragma unroll
    for (int off = 16; off; off >>= 1) s += __shfl_xor_sync(0xFFFFFFFFu, s, off);
    if (lane == 0) out[(size_t)gw * (DIM + 1) + DIM] = s * (1.f / 3.f);
}

// ---------------- launch ----------------
extern "C" void kernel_launch(void* const* d_in, const int* in_sizes, int n_in,
                              void* d_out, int out_size) {
    const float* aug = (const float*)d_in[1];
    const float* eps = (const float*)d_in[2];
    const float* W1  = (const float*)d_in[3];
    const float* b1  = (const float*)d_in[4];
    const float* W2  = (const float*)d_in[5];
    const float* b2  = (const float*)d_in[6];
    const float* W3  = (const float*)d_in[7];
    const float* b3  = (const float*)d_in[8];
    float* out = (float*)d_out;

    __half *zh, *h1h, *h2h, *d2h, *d1h;
    cudaGetSymbolAddress((void**)&zh,  g_zh);
    cudaGetSymbolAddress((void**)&h1h, g_h1h);
    cudaGetSymbolAddress((void**)&h2h, g_h2h);
    cudaGetSymbolAddress((void**)&d2h, g_d2h);
    cudaGetSymbolAddress((void**)&d1h, g_d1h);
    float *gg, *v3p;
    cudaGetSymbolAddress((void**)&gg,  g_g);
    cudaGetSymbolAddress((void**)&v3p, g_v3);
    __half *w1h, *w2h, *w3h, *w2th, *w1th;
    cudaGetSymbolAddress((void**)&w1h,  g_W1h);
    cudaGetSymbolAddress((void**)&w2h,  g_W2h);
    cudaGetSymbolAddress((void**)&w3h,  g_W3h);
    cudaGetSymbolAddress((void**)&w2th, g_W2Th);
    cudaGetSymbolAddress((void**)&w1th, g_W1Th);

    cudaFuncSetAttribute(mma_gemm<EPI_H1>,   cudaFuncAttributeMaxDynamicSharedMemorySize, SMEM_TOTAL);
    cudaFuncSetAttribute(mma_gemm<EPI_H2D2>, cudaFuncAttributeMaxDynamicSharedMemorySize, SMEM_TOTAL);
    cudaFuncSetAttribute(mma_gemm<EPI_OUT>,  cudaFuncAttributeMaxDynamicSharedMemorySize, SMEM_TOTAL);
    cudaFuncSetAttribute(mma_gemm<EPI_D1>,   cudaFuncAttributeMaxDynamicSharedMemorySize, SMEM_TOTAL);
    cudaFuncSetAttribute(mma_gemm<EPI_G>,    cudaFuncAttributeMaxDynamicSharedMemorySize, SMEM_TOTAL);

    // launch 0: all weight prep in one grid
    k_prep<<<PB_V3, 256>>>(W1, W2, W3);
    // launch 1: activation pack
    k_pack_z<<<BATCH, DIM>>>(aug);

    // launch 2 — G1: h1 = tanh(z @ W1^T + b1)   [K=512]
    mma_gemm<EPI_H1><<<dim3(HID / BN, BATCH / BM), THREADS, SMEM_TOTAL>>>(
        zh, w1h, b1, nullptr, nullptr, 0,
        h1h, nullptr, nullptr, DIM, HID);
    // launch 3 — G2: h2 = tanh(h1 @ W2^T + b2); d2 = v3*(1-h2^2)
    mma_gemm<EPI_H2D2><<<dim3(HID / BN, BATCH / BM), THREADS, SMEM_TOTAL>>>(
        h1h, w2h, b2, v3p, nullptr, 0,
        h2h, d2h, nullptr, HID, HID);
    // launch 4 — G3: dz_dt = h2 @ W3^T + b3 -> out[:, :512] (ldc=513)
    mma_gemm<EPI_OUT><<<dim3(DIM / BN, BATCH / BM), THREADS, SMEM_TOTAL>>>(
        h2h, w3h, b3, nullptr, out, DIM + 1,
        nullptr, nullptr, nullptr, HID, 0);
    // launch 5 — G4: dh1 = d2 @ W2; d1 = dh1*(1-h1^2)   <-- ncu -s 5 captures this
    mma_gemm<EPI_D1><<<dim3(HID / BN, BATCH / BM), THREADS, SMEM_TOTAL>>>(
        d2h, w2th, nullptr, nullptr, nullptr, 0,
        d1h, nullptr, h1h, HID, HID);
    // launch 6 — G5: g = d1 @ W1
    mma_gemm<EPI_G><<<dim3(DIM / BN, BATCH / BM), THREADS, SMEM_TOTAL>>>(
        d1h, w1th, nullptr, nullptr, gg, DIM,
        nullptr, nullptr, nullptr, HID, 0);

    // launch 7 — trace column
    k_trace<<<BATCH / 8, 256>>>(eps, out);
}